// round 6
// baseline (speedup 1.0000x reference)
#include <cuda_runtime.h>
#include <math.h>

#define HB 65536   // H*B floats per t-slab

// ---- scratch ----
__device__ float g_WstackT[512 * 3072];   // [k][j] for gemmA (fp32)
__device__ float g_Wr0[1024 * 1024];      // tf32-rounded [n][k]  (Wh0)
__device__ float g_Wr1[1024 * 2048];      // [n][k] k<1024: Wi12[0], else Wh1
__device__ float g_Wr2[1024 * 2048];      // [n][k] k<1024: Wi12[1], else Wh2
__device__ float g_b0[1024], g_b1[1024], g_b2[1024];
__device__ float g_A0[256 * HB], g_A1[256 * HB], g_A2[256 * HB];  // [t][b][h] fp32
__device__ float g_H0[257 * HB];          // [i][b][h]: H0[i]=h0[i-1] (tf32-rounded)
__device__ float g_H1[256 * HB];
__device__ float g_H2[256 * HB];
__device__ float g_P[320 * 8192];         // partials [task][b(64)][n(128)]
__device__ unsigned g_ctr[258 * 24];      // per-slot, per-group completion counters

__device__ __forceinline__ float rnd_tf32(float x) {
    unsigned r;
    asm("cvt.rna.tf32.f32 %0, %1;" : "=r"(r) : "f"(x));
    return __uint_as_float(r);
}

__global__ void prep_kernel(const float* __restrict__ Wi0, const float* __restrict__ Wi12,
                            const float* __restrict__ bi,  const float* __restrict__ Ws,
                            const float* __restrict__ bs,  const float* __restrict__ Wh,
                            const float* __restrict__ bh,  const float* __restrict__ noise) {
    int tid = blockIdx.x * blockDim.x + threadIdx.x, nthr = gridDim.x * blockDim.x;
    for (int i = tid; i < 512 * 3072; i += nthr) {
        int k = i / 3072, j = i % 3072;
        float v;
        if (j < 1024)      v = Wi0[j * 512 + k] + Ws[j * 512 + k];
        else if (j < 2048) v = Ws[524288 + (j - 1024) * 512 + k];
        else               v = Ws[1048576 + (j - 2048) * 512 + k];
        g_WstackT[i] = v;
    }
    for (int i = tid; i < 1024 * 1024; i += nthr)
        g_Wr0[i] = rnd_tf32(Wh[i]);                    // [n][k] same layout
    for (int i = tid; i < 1024 * 2048; i += nthr) {
        int n = i >> 11, k = i & 2047;
        g_Wr1[i] = rnd_tf32((k < 1024) ? Wi12[n * 1024 + k] : Wh[1048576 + n * 1024 + (k - 1024)]);
        g_Wr2[i] = rnd_tf32((k < 1024) ? Wi12[1048576 + n * 1024 + k] : Wh[2097152 + n * 1024 + (k - 1024)]);
    }
    for (int i = tid; i < 1024; i += nthr) {
        g_b0[i] = bi[i] + bs[i] + bh[i];
        g_b1[i] = bi[1024 + i] + bs[1024 + i] + bh[1024 + i];
        g_b2[i] = bi[2048 + i] + bs[2048 + i] + bh[2048 + i];
    }
    for (int i = tid; i < 258 * 24; i += nthr) g_ctr[i] = 0u;
    for (int i = tid; i < HB; i += nthr) {             // [b][h] natural layout
        g_H0[i] = rnd_tf32(noise[i]);
        g_H1[i] = rnd_tf32(noise[3 * HB + i]);
        g_H2[2 * HB + i] = rnd_tf32(noise[6 * HB + i]);
    }
}

// A_l[t][b][h] = xcomb_l[t] @ WstackT[:, l*1024+h] + bias_l[h]   (fp32)
__global__ void __launch_bounds__(128) gemmA_kernel(const float* __restrict__ x) {
    __shared__ float Ws_[16][128];
    __shared__ float Xs_[16][64];
    __shared__ float T_[64][65];
    const int t = blockIdx.y, hbase = blockIdx.x * 128, l = blockIdx.z;
    const int tid = threadIdx.x, tn = tid & 15, tb = tid >> 4;
    float acc[8][8];
#pragma unroll
    for (int a = 0; a < 8; a++)
#pragma unroll
        for (int b = 0; b < 8; b++) acc[a][b] = 0.f;

    for (int kk = 0; kk < 512; kk += 16) {
#pragma unroll
        for (int i = 0; i < 4; i++) {
            int f4 = i * 128 + tid, k = f4 >> 5, n4 = f4 & 31;
            *(float4*)&Ws_[k][n4 * 4] =
                *(const float4*)&g_WstackT[(kk + k) * 3072 + l * 1024 + hbase + n4 * 4];
        }
#pragma unroll
        for (int i = 0; i < 2; i++) {
            int f4 = i * 128 + tid, b = f4 >> 2, k4 = f4 & 3;
            const float* xb = x + b * (256 * 512) + kk + k4 * 4;
            float4 v = make_float4(0.f, 0.f, 0.f, 0.f);
            if (l == 0) {
                if (t + 3 < 256) v = *(const float4*)&xb[(t + 3) * 512];
            } else if (l == 1) {
                if (t + 2 < 256) { float4 u = *(const float4*)&xb[(t + 2) * 512]; v.x += u.x; v.y += u.y; v.z += u.z; v.w += u.w; }
                if (t + 3 < 256) { float4 u = *(const float4*)&xb[(t + 3) * 512]; v.x += u.x; v.y += u.y; v.z += u.z; v.w += u.w; }
                v.x *= 0.5f; v.y *= 0.5f; v.z *= 0.5f; v.w *= 0.5f;
            } else {
#pragma unroll
                for (int dt = 0; dt < 4; dt++)
                    if (t + dt < 256) { float4 u = *(const float4*)&xb[(t + dt) * 512]; v.x += u.x; v.y += u.y; v.z += u.z; v.w += u.w; }
                v.x *= 0.25f; v.y *= 0.25f; v.z *= 0.25f; v.w *= 0.25f;
            }
            Xs_[k4 * 4 + 0][b] = v.x; Xs_[k4 * 4 + 1][b] = v.y;
            Xs_[k4 * 4 + 2][b] = v.z; Xs_[k4 * 4 + 3][b] = v.w;
        }
        __syncthreads();
#pragma unroll
        for (int k = 0; k < 16; k++) {
            float nf[8], bf[8];
            *(float4*)&nf[0] = *(float4*)&Ws_[k][tn * 4];
            *(float4*)&nf[4] = *(float4*)&Ws_[k][64 + tn * 4];
            *(float4*)&bf[0] = *(float4*)&Xs_[k][tb * 4];
            *(float4*)&bf[4] = *(float4*)&Xs_[k][32 + tb * 4];
#pragma unroll
            for (int a = 0; a < 8; a++)
#pragma unroll
                for (int b = 0; b < 8; b++) acc[a][b] += nf[a] * bf[b];
        }
        __syncthreads();
    }
    float* A = (l == 0) ? g_A0 : (l == 1) ? g_A1 : g_A2;
    const float* bl = (l == 0) ? g_b0 : (l == 1) ? g_b1 : g_b2;
    // transpose epilogue -> A[t][b][h]
    for (int r = 0; r < 2; r++) {
        __syncthreads();
#pragma unroll
        for (int a = 0; a < 4; a++) {
            int hl = tn * 4 + a;
            float bv = bl[hbase + r * 64 + hl];
#pragma unroll
            for (int c = 0; c < 8; c++) {
                int b = (c < 4) ? (tb * 4 + c) : (32 + tb * 4 + (c - 4));
                T_[hl][b] = acc[r * 4 + a][c] + bv;
            }
        }
        __syncthreads();
#pragma unroll
        for (int j = 0; j < 32; j++) {
            int elem = j * 128 + tid;
            int b = elem >> 6, hl = elem & 63;
            A[t * HB + b * 1024 + hbase + r * 64 + hl] = T_[hl][b];
        }
    }
}

#define MMA_TF32(d, a, b) \
    asm volatile("mma.sync.aligned.m16n8k8.row.col.f32.tf32.tf32.f32 " \
                 "{%0,%1,%2,%3},{%4,%5,%6,%7},{%8,%9},{%0,%1,%2,%3};" \
                 : "+f"(d[0]), "+f"(d[1]), "+f"(d[2]), "+f"(d[3]) \
                 : "r"(a[0]), "r"(a[1]), "r"(a[2]), "r"(a[3]), "r"(b[0]), "r"(b[1]))

// Fused per-slot kernel: 320 mma tasks; the last-finishing block of each
// (layer, ntile) group reduces partials + A, applies tanh, writes state.
__global__ void __launch_bounds__(128) slot_fused_kernel(int s) {
    const int task = blockIdx.x;
    int layer, ntile, kc;
    if (task < 64)       { layer = 0; ntile = task >> 3; kc = task & 7; }
    else if (task < 192) { layer = 1; int r = task - 64;  ntile = r >> 4; kc = r & 15; }
    else                 { layer = 2; int r = task - 192; ntile = r >> 4; kc = r & 15; }
    if (layer == 0) { if (s > 255) return; }
    else if (layer == 1) { if (s < 2 || s > 256) return; }
    else { if (s < 5 || s > 257) return; }

    const int kst = kc * 128, nbase = ntile * 128;
    const float* wsrc; int K;
    if (layer == 0)      { wsrc = g_Wr0; K = 1024; }
    else if (layer == 1) { wsrc = g_Wr1; K = 2048; }
    else                 { wsrc = g_Wr2; K = 2048; }
    const float* hbasep; int koff;
    if (layer == 0)      { hbasep = g_H0 + s * HB; koff = kst; }
    else if (layer == 1) {
        if (kst < 1024) { hbasep = g_H0 + s * HB; koff = kst; }
        else            { hbasep = g_H1 + (s - 2) * HB; koff = kst - 1024; }
    } else {
        if (kst < 1024) { hbasep = g_H1 + (s - 2) * HB; koff = kst; }
        else            { hbasep = g_H2 + (s - 3) * HB; koff = kst - 1024; }
    }

    __shared__ float Bs[128 * 17];   // [n][k16] pad 17
    __shared__ float As[64 * 17];    // [b][k16] pad 17
    __shared__ int is_last_s;
    const int tid = threadIdx.x, warp = tid >> 5, lane = tid & 31;
    const int gid = lane >> 2, tig = lane & 3;

    float acc[4][4][4];
#pragma unroll
    for (int mi = 0; mi < 4; mi++)
#pragma unroll
        for (int nj = 0; nj < 4; nj++)
#pragma unroll
            for (int q = 0; q < 4; q++) acc[mi][nj][q] = 0.f;

    const float* bsrc = wsrc + (nbase + tid) * K + kst;
    const float* asrc = hbasep + tid * 1024 + koff;   // tid<64 only
    float4 br[4], ar[4];
#pragma unroll
    for (int q = 0; q < 4; q++) br[q] = *(const float4*)(bsrc + q * 4);
    if (tid < 64)
#pragma unroll
        for (int q = 0; q < 4; q++) ar[q] = *(const float4*)(asrc + q * 4);

    for (int step = 0; step < 8; step++) {
        __syncthreads();
        {
            float* bp = &Bs[tid * 17];
#pragma unroll
            for (int q = 0; q < 4; q++) {
                bp[q * 4 + 0] = br[q].x; bp[q * 4 + 1] = br[q].y;
                bp[q * 4 + 2] = br[q].z; bp[q * 4 + 3] = br[q].w;
            }
            if (tid < 64) {
                float* ap = &As[tid * 17];
#pragma unroll
                for (int q = 0; q < 4; q++) {
                    ap[q * 4 + 0] = ar[q].x; ap[q * 4 + 1] = ar[q].y;
                    ap[q * 4 + 2] = ar[q].z; ap[q * 4 + 3] = ar[q].w;
                }
            }
        }
        __syncthreads();
        if (step < 7) {
#pragma unroll
            for (int q = 0; q < 4; q++) br[q] = *(const float4*)(bsrc + (step + 1) * 16 + q * 4);
            if (tid < 64)
#pragma unroll
                for (int q = 0; q < 4; q++) ar[q] = *(const float4*)(asrc + (step + 1) * 16 + q * 4);
        }
#pragma unroll
        for (int sub = 0; sub < 2; sub++) {
            unsigned a[4][4], b[4][2];
            int ko = sub * 8 + tig;
#pragma unroll
            for (int mi = 0; mi < 4; mi++) {
                int r0 = mi * 16 + gid;
                a[mi][0] = __float_as_uint(As[r0 * 17 + ko]);
                a[mi][1] = __float_as_uint(As[(r0 + 8) * 17 + ko]);
                a[mi][2] = __float_as_uint(As[r0 * 17 + ko + 4]);
                a[mi][3] = __float_as_uint(As[(r0 + 8) * 17 + ko + 4]);
            }
#pragma unroll
            for (int nj = 0; nj < 4; nj++) {
                int n0 = warp * 32 + nj * 8 + gid;
                b[nj][0] = __float_as_uint(Bs[n0 * 17 + ko]);
                b[nj][1] = __float_as_uint(Bs[n0 * 17 + ko + 4]);
            }
#pragma unroll
            for (int mi = 0; mi < 4; mi++)
#pragma unroll
                for (int nj = 0; nj < 4; nj++) MMA_TF32(acc[mi][nj], a[mi], b[nj]);
        }
    }
    // partials [b][n]
    float* pb = g_P + task * 8192;
#pragma unroll
    for (int mi = 0; mi < 4; mi++)
#pragma unroll
        for (int nj = 0; nj < 4; nj++) {
            int n = warp * 32 + nj * 8 + 2 * tig;
            int b0 = mi * 16 + gid;
            *(float2*)&pb[b0 * 128 + n] = make_float2(acc[mi][nj][0], acc[mi][nj][1]);
            *(float2*)&pb[(b0 + 8) * 128 + n] = make_float2(acc[mi][nj][2], acc[mi][nj][3]);
        }

    // ---- completion counting: last block of the group reduces ----
    int group, tbase, nk;
    if (layer == 0)      { group = ntile;      tbase = ntile * 8;        nk = 8; }
    else if (layer == 1) { group = 8 + ntile;  tbase = 64 + ntile * 16;  nk = 16; }
    else                 { group = 16 + ntile; tbase = 192 + ntile * 16; nk = 16; }

    __threadfence();
    __syncthreads();
    if (tid == 0) {
        unsigned old = atomicAdd(&g_ctr[s * 24 + group], 1u);
        is_last_s = (old == (unsigned)(nk - 1));
    }
    __syncthreads();
    if (!is_last_s) return;
    __threadfence();

    const float* A = (layer == 0) ? g_A0 : (layer == 1) ? g_A1 : g_A2;
    int t = (layer == 0) ? s : (layer == 1) ? (s - 1) : (s - 2);
    float* dst = (layer == 0) ? (g_H0 + (s + 1) * HB)
               : (layer == 1) ? (g_H1 + (s - 1) * HB)
                              : (g_H2 + (s - 2) * HB);
    for (int pos = tid; pos < 2048; pos += 128) {
        int b = pos >> 5, nl4 = (pos & 31) * 4;
        float4 sum = *(const float4*)&A[t * HB + b * 1024 + nbase + nl4];
        for (int k = 0; k < nk; k++) {
            float4 p = *(const float4*)&g_P[(tbase + k) * 8192 + b * 128 + nl4];
            sum.x += p.x; sum.y += p.y; sum.z += p.z; sum.w += p.w;
        }
        *(float4*)&dst[b * 1024 + nbase + nl4] = make_float4(
            rnd_tf32(tanhf(sum.x)), rnd_tf32(tanhf(sum.y)),
            rnd_tf32(tanhf(sum.z)), rnd_tf32(tanhf(sum.w)));
    }
}

// out[l][b][i] = sum_h hs[b][h]*Wo[i][h] + bo[i]; hs in [b][h]
__global__ void __launch_bounds__(256) out_kernel(const float* __restrict__ Wo,
                                                  const float* __restrict__ bo,
                                                  float* __restrict__ out) {
    __shared__ float Hs[64][65];
    __shared__ float Wos[32][65];
    const int l = blockIdx.y, ibase = blockIdx.x * 32;
    const float* hsrc = (l == 0) ? g_H0 + 256 * HB : (l == 1) ? g_H1 + 255 * HB : g_H2 + 255 * HB;
    const int tid = threadIdx.x, i = tid & 31, brow = tid >> 5;
    float acc[8];
#pragma unroll
    for (int q = 0; q < 8; q++) acc[q] = 0.f;
    for (int kc = 0; kc < 1024; kc += 64) {
        __syncthreads();
#pragma unroll
        for (int j = 0; j < 16; j++) {
            int e = j * 256 + tid, b = e >> 6, k = e & 63;
            Hs[b][k] = hsrc[b * 1024 + kc + k];
        }
#pragma unroll
        for (int j = 0; j < 8; j++) {
            int e = j * 256 + tid, ii = e >> 6, k = e & 63;
            Wos[ii][k] = Wo[(ibase + ii) * 1024 + kc + k];
        }
        __syncthreads();
#pragma unroll
        for (int k = 0; k < 64; k++) {
            float w = Wos[i][k];
#pragma unroll
            for (int bb = 0; bb < 8; bb++) acc[bb] += Hs[bb * 8 + brow][k] * w;
        }
    }
    float bv = bo[ibase + i];
#pragma unroll
    for (int bb = 0; bb < 8; bb++)
        out[l * 32768 + (bb * 8 + brow) * 512 + ibase + i] = acc[bb] + bv;
}

extern "C" void kernel_launch(void* const* d_in, const int* in_sizes, int n_in,
                              void* d_out, int out_size) {
    const float* x     = (const float*)d_in[0];
    const float* noise = (const float*)d_in[1];
    const float* Wi0   = (const float*)d_in[2];
    const float* Wi12  = (const float*)d_in[3];
    const float* bi    = (const float*)d_in[4];
    const float* Ws    = (const float*)d_in[5];
    const float* bs    = (const float*)d_in[6];
    const float* Wh    = (const float*)d_in[7];
    const float* bh    = (const float*)d_in[8];
    const float* Wo    = (const float*)d_in[9];
    const float* bo    = (const float*)d_in[10];
    float* out = (float*)d_out;

    prep_kernel<<<512, 256>>>(Wi0, Wi12, bi, Ws, bs, Wh, bh, noise);
    gemmA_kernel<<<dim3(8, 256, 3), 128>>>(x);
    for (int s = 0; s < 258; s++)
        slot_fused_kernel<<<320, 128>>>(s);
    out_kernel<<<dim3(16, 3), 256>>>(Wo, bo, out);
}

// round 8
// speedup vs baseline: 2.0774x; 2.0774x over previous
#include <cuda_runtime.h>
#include <math.h>

#define HB 65536   // H*B floats per t-slab
#define NU 2560    // 16-k-row units: L0 8 tiles x 64u, L1 8 x 128u, L2 8 x 128u

// ---- scratch ----
__device__ float g_WstackT[512 * 3072];   // [k][j] for gemmA (fp32)
__device__ float g_Wr0[1024 * 1024];      // tf32-rounded [n][k]  (Wh0)
__device__ float g_Wr1[1024 * 2048];      // [n][k] k<1024: Wi12[0], else Wh1
__device__ float g_Wr2[1024 * 2048];      // [n][k] k<1024: Wi12[1], else Wh2
__device__ float g_b0[1024], g_b1[1024], g_b2[1024];
__device__ float g_A0[256 * HB], g_A1[256 * HB], g_A2[256 * HB];  // [t][b][h] fp32
__device__ float g_H0[257 * HB];          // [i][b][h]: H0[i]=h0[i-1] (tf32-rounded)
__device__ float g_H1[256 * HB];
__device__ float g_H2[256 * HB];
__device__ float g_P[320 * 2 * 8192];     // partials [blk][seg][b(64)][n(128)]
__device__ unsigned g_bar[516];

__device__ __forceinline__ float rnd_tf32(float x) {
    unsigned r;
    asm("cvt.rna.tf32.f32 %0, %1;" : "=r"(r) : "f"(x));
    return __uint_as_float(r);
}
__device__ __forceinline__ int ustart(int b, int nblk) {
    return (int)(((long long)b * NU) / nblk);
}

__global__ void prep_kernel(const float* __restrict__ Wi0, const float* __restrict__ Wi12,
                            const float* __restrict__ bi,  const float* __restrict__ Ws,
                            const float* __restrict__ bs,  const float* __restrict__ Wh,
                            const float* __restrict__ bh,  const float* __restrict__ noise) {
    int tid = blockIdx.x * blockDim.x + threadIdx.x, nthr = gridDim.x * blockDim.x;
    for (int i = tid; i < 512 * 3072; i += nthr) {
        int k = i / 3072, j = i % 3072;
        float v;
        if (j < 1024)      v = Wi0[j * 512 + k] + Ws[j * 512 + k];
        else if (j < 2048) v = Ws[524288 + (j - 1024) * 512 + k];
        else               v = Ws[1048576 + (j - 2048) * 512 + k];
        g_WstackT[i] = v;
    }
    for (int i = tid; i < 1024 * 1024; i += nthr)
        g_Wr0[i] = rnd_tf32(Wh[i]);
    for (int i = tid; i < 1024 * 2048; i += nthr) {
        int n = i >> 11, k = i & 2047;
        g_Wr1[i] = rnd_tf32((k < 1024) ? Wi12[n * 1024 + k] : Wh[1048576 + n * 1024 + (k - 1024)]);
        g_Wr2[i] = rnd_tf32((k < 1024) ? Wi12[1048576 + n * 1024 + k] : Wh[2097152 + n * 1024 + (k - 1024)]);
    }
    for (int i = tid; i < 1024; i += nthr) {
        g_b0[i] = bi[i] + bs[i] + bh[i];
        g_b1[i] = bi[1024 + i] + bs[1024 + i] + bh[1024 + i];
        g_b2[i] = bi[2048 + i] + bs[2048 + i] + bh[2048 + i];
    }
    for (int i = tid; i < 516; i += nthr) g_bar[i] = 0u;
    for (int i = tid; i < HB; i += nthr) {
        g_H0[i] = rnd_tf32(noise[i]);
        g_H1[i] = rnd_tf32(noise[3 * HB + i]);
        g_H2[2 * HB + i] = rnd_tf32(noise[6 * HB + i]);
    }
}

// A_l[t][b][h] = xcomb_l[t] @ WstackT[:, l*1024+h] + bias_l[h]   (fp32)
__global__ void __launch_bounds__(128) gemmA_kernel(const float* __restrict__ x) {
    __shared__ float Ws_[16][128];
    __shared__ float Xs_[16][64];
    __shared__ float T_[64][65];
    const int t = blockIdx.y, hbase = blockIdx.x * 128, l = blockIdx.z;
    const int tid = threadIdx.x, tn = tid & 15, tb = tid >> 4;
    float acc[8][8];
#pragma unroll
    for (int a = 0; a < 8; a++)
#pragma unroll
        for (int b = 0; b < 8; b++) acc[a][b] = 0.f;

    for (int kk = 0; kk < 512; kk += 16) {
#pragma unroll
        for (int i = 0; i < 4; i++) {
            int f4 = i * 128 + tid, k = f4 >> 5, n4 = f4 & 31;
            *(float4*)&Ws_[k][n4 * 4] =
                *(const float4*)&g_WstackT[(kk + k) * 3072 + l * 1024 + hbase + n4 * 4];
        }
#pragma unroll
        for (int i = 0; i < 2; i++) {
            int f4 = i * 128 + tid, b = f4 >> 2, k4 = f4 & 3;
            const float* xb = x + b * (256 * 512) + kk + k4 * 4;
            float4 v = make_float4(0.f, 0.f, 0.f, 0.f);
            if (l == 0) {
                if (t + 3 < 256) v = *(const float4*)&xb[(t + 3) * 512];
            } else if (l == 1) {
                if (t + 2 < 256) { float4 u = *(const float4*)&xb[(t + 2) * 512]; v.x += u.x; v.y += u.y; v.z += u.z; v.w += u.w; }
                if (t + 3 < 256) { float4 u = *(const float4*)&xb[(t + 3) * 512]; v.x += u.x; v.y += u.y; v.z += u.z; v.w += u.w; }
                v.x *= 0.5f; v.y *= 0.5f; v.z *= 0.5f; v.w *= 0.5f;
            } else {
#pragma unroll
                for (int dt = 0; dt < 4; dt++)
                    if (t + dt < 256) { float4 u = *(const float4*)&xb[(t + dt) * 512]; v.x += u.x; v.y += u.y; v.z += u.z; v.w += u.w; }
                v.x *= 0.25f; v.y *= 0.25f; v.z *= 0.25f; v.w *= 0.25f;
            }
            Xs_[k4 * 4 + 0][b] = v.x; Xs_[k4 * 4 + 1][b] = v.y;
            Xs_[k4 * 4 + 2][b] = v.z; Xs_[k4 * 4 + 3][b] = v.w;
        }
        __syncthreads();
#pragma unroll
        for (int k = 0; k < 16; k++) {
            float nf[8], bf[8];
            *(float4*)&nf[0] = *(float4*)&Ws_[k][tn * 4];
            *(float4*)&nf[4] = *(float4*)&Ws_[k][64 + tn * 4];
            *(float4*)&bf[0] = *(float4*)&Xs_[k][tb * 4];
            *(float4*)&bf[4] = *(float4*)&Xs_[k][32 + tb * 4];
#pragma unroll
            for (int a = 0; a < 8; a++)
#pragma unroll
                for (int b = 0; b < 8; b++) acc[a][b] += nf[a] * bf[b];
        }
        __syncthreads();
    }
    float* A = (l == 0) ? g_A0 : (l == 1) ? g_A1 : g_A2;
    const float* bl = (l == 0) ? g_b0 : (l == 1) ? g_b1 : g_b2;
    for (int r = 0; r < 2; r++) {
        __syncthreads();
#pragma unroll
        for (int a = 0; a < 4; a++) {
            int hl = tn * 4 + a;
            float bv = bl[hbase + r * 64 + hl];
#pragma unroll
            for (int c = 0; c < 8; c++) {
                int b = (c < 4) ? (tb * 4 + c) : (32 + tb * 4 + (c - 4));
                T_[hl][b] = acc[r * 4 + a][c] + bv;
            }
        }
        __syncthreads();
#pragma unroll
        for (int j = 0; j < 32; j++) {
            int elem = j * 128 + tid;
            int b = elem >> 6, hl = elem & 63;
            A[t * HB + b * 1024 + hbase + r * 64 + hl] = T_[hl][b];
        }
    }
}

#define MMA_TF32(d, a, b) \
    asm volatile("mma.sync.aligned.m16n8k8.row.col.f32.tf32.tf32.f32 " \
                 "{%0,%1,%2,%3},{%4,%5,%6,%7},{%8,%9},{%0,%1,%2,%3};" \
                 : "+f"(d[0]), "+f"(d[1]), "+f"(d[2]), "+f"(d[3]) \
                 : "r"(a[0]), "r"(a[1]), "r"(a[2]), "r"(a[3]), "r"(b[0]), "r"(b[1]))

__device__ __forceinline__ void gbar(int i, int nblk) {
    __syncthreads();
    if (threadIdx.x == 0) {
        __threadfence();
        atomicAdd(&g_bar[i], 1u);
        while (*((volatile unsigned*)&g_bar[i]) < (unsigned)nblk) __nanosleep(64);
        __threadfence();
    }
    __syncthreads();
}

// tile info from unit u
__device__ __forceinline__ void tile_of(int u, int& layer, int& ntile, int& kst, int& tend) {
    if (u < 512)       { layer = 0; ntile = u >> 6; kst = (u & 63) * 16; tend = (ntile + 1) * 64; }
    else if (u < 1536) { int r = u - 512;  layer = 1; ntile = r >> 7; kst = (r & 127) * 16; tend = 512 + (ntile + 1) * 128; }
    else               { int r = u - 1536; layer = 2; ntile = r >> 7; kst = (r & 127) * 16; tend = 1536 + (ntile + 1) * 128; }
}

#define PAD 20   // row stride 80B: 16B-aligned for float4 stores, conflict-free reads

__global__ void __launch_bounds__(256) persist_kernel(int nblk) {
    __shared__ float Bs[128][PAD];
    __shared__ float As[64][PAD];
    __shared__ int tblP[24][24];
    __shared__ int tblCnt[24];
    const int tid = threadIdx.x, bid = blockIdx.x;
    const int warp = tid >> 5, lane = tid & 31;
    const int gid = lane >> 2, tig = lane & 3;
    const int u0 = ustart(bid, nblk), u1 = ustart(bid + 1, nblk);

    if (tid < 24) {
        int g = tid, t0, t1;
        if (g < 8)       { t0 = g * 64;                t1 = t0 + 64; }
        else if (g < 16) { t0 = 512 + (g - 8) * 128;   t1 = t0 + 128; }
        else             { t0 = 1536 + (g - 16) * 128; t1 = t0 + 128; }
        int cnt = 0;
        for (int bb = 0; bb < nblk; bb++) {
            int s0 = ustart(bb, nblk), s1 = ustart(bb + 1, nblk);
            if (s0 < t1 && s1 > t0) {
                int seg = (s0 < t0) ? 1 : 0;
                tblP[g][cnt++] = (bb * 2 + seg) * 8192;
            }
        }
        tblCnt[g] = cnt;
    }
    __syncthreads();

    for (int s = 0; s < 258; s++) {
        // ================= GEMM phase =================
        int u = u0, seg = 0;
        while (u < u1) {
            int layer, ntile, kst, tend;
            tile_of(u, layer, ntile, kst, tend);
            int uend = (u1 < tend) ? u1 : tend;
            int klen = (uend - u) * 16;
            bool valid = (layer == 0) ? (s <= 255)
                       : (layer == 1) ? (s >= 2 && s <= 256)
                                      : (s >= 5 && s <= 257);
            if (valid) {
                const int nbase = ntile * 128;
                const float* wsrc; int K;
                if (layer == 0)      { wsrc = g_Wr0; K = 1024; }
                else if (layer == 1) { wsrc = g_Wr1; K = 2048; }
                else                 { wsrc = g_Wr2; K = 2048; }
                const float *hA, *hB = 0;
                if (layer == 0)      { hA = g_H0 + s * HB; }
                else if (layer == 1) { hA = g_H0 + s * HB;       hB = g_H1 + (s - 2) * HB; }
                else                 { hA = g_H1 + (s - 2) * HB; hB = g_H2 + (s - 3) * HB; }

                const int brow = tid >> 1, bhalf = tid & 1;
                const int arow = tid >> 2, aq = tid & 3;
                const float* bsrcT = wsrc + (nbase + brow) * K + bhalf * 8;

                float acc[4][2][4];
#pragma unroll
                for (int mi = 0; mi < 4; mi++)
#pragma unroll
                    for (int nj = 0; nj < 2; nj++)
#pragma unroll
                        for (int q = 0; q < 4; q++) acc[mi][nj][q] = 0.f;

                int steps = klen >> 4;
                int kcur = kst;
                float4 br0 = *(const float4*)(bsrcT + kcur);
                float4 br1 = *(const float4*)(bsrcT + kcur + 4);
                int kg = kcur + aq * 4;
                float4 arv = (layer == 0 || kg < 1024)
                           ? *(const float4*)(hA + arow * 1024 + kg)
                           : *(const float4*)(hB + arow * 1024 + kg - 1024);
                for (int step = 0; step < steps; step++) {
                    __syncthreads();
                    *(float4*)&Bs[brow][bhalf * 8]     = br0;
                    *(float4*)&Bs[brow][bhalf * 8 + 4] = br1;
                    *(float4*)&As[arow][aq * 4]        = arv;
                    __syncthreads();
                    if (step + 1 < steps) {
                        int kn = kcur + 16;
                        br0 = *(const float4*)(bsrcT + kn);
                        br1 = *(const float4*)(bsrcT + kn + 4);
                        int kg2 = kn + aq * 4;
                        arv = (layer == 0 || kg2 < 1024)
                            ? *(const float4*)(hA + arow * 1024 + kg2)
                            : *(const float4*)(hB + arow * 1024 + kg2 - 1024);
                    }
#pragma unroll
                    for (int sub = 0; sub < 2; sub++) {
                        int ko = sub * 8 + tig;
                        unsigned a[4][4], b[2][2];
#pragma unroll
                        for (int mi = 0; mi < 4; mi++) {
                            int r0 = mi * 16 + gid;
                            a[mi][0] = __float_as_uint(As[r0][ko]);
                            a[mi][1] = __float_as_uint(As[r0 + 8][ko]);
                            a[mi][2] = __float_as_uint(As[r0][ko + 4]);
                            a[mi][3] = __float_as_uint(As[r0 + 8][ko + 4]);
                        }
#pragma unroll
                        for (int nj = 0; nj < 2; nj++) {
                            int n0 = warp * 16 + nj * 8 + gid;
                            b[nj][0] = __float_as_uint(Bs[n0][ko]);
                            b[nj][1] = __float_as_uint(Bs[n0][ko + 4]);
                        }
#pragma unroll
                        for (int mi = 0; mi < 4; mi++)
#pragma unroll
                            for (int nj = 0; nj < 2; nj++) MMA_TF32(acc[mi][nj], a[mi], b[nj]);
                    }
                    kcur += 16;
                }
                float* pb = g_P + (bid * 2 + seg) * 8192;
#pragma unroll
                for (int mi = 0; mi < 4; mi++)
#pragma unroll
                    for (int nj = 0; nj < 2; nj++) {
                        int n = warp * 16 + nj * 8 + 2 * tig;
                        int b0 = mi * 16 + gid;
                        *(float2*)&pb[b0 * 128 + n]       = make_float2(acc[mi][nj][0], acc[mi][nj][1]);
                        *(float2*)&pb[(b0 + 8) * 128 + n] = make_float2(acc[mi][nj][2], acc[mi][nj][3]);
                    }
            }
            u = uend;
            seg++;
        }
        gbar(2 * s, nblk);

        // ================= reduce phase =================
        for (int idx = bid * 256 + tid; idx < 49152; idx += nblk * 256) {
            int g = idx >> 11, e = idx & 2047;
            int layer = g >> 3, ntile = g & 7;
            bool valid = (layer == 0) ? (s <= 255)
                       : (layer == 1) ? (s >= 2 && s <= 256)
                                      : (s >= 5 && s <= 257);
            if (!valid) continue;
            int b = e >> 5, nl4 = (e & 31) * 4;
            int nbase = ntile * 128;
            const float* A = (layer == 0) ? g_A0 : (layer == 1) ? g_A1 : g_A2;
            int t = (layer == 0) ? s : (layer == 1) ? (s - 1) : (s - 2);
            float4 sum = *(const float4*)&A[t * HB + b * 1024 + nbase + nl4];
            int cnt = tblCnt[g];
            for (int j = 0; j < cnt; j++) {
                float4 p = __ldcg((const float4*)&g_P[tblP[g][j] + b * 128 + nl4]);
                sum.x += p.x; sum.y += p.y; sum.z += p.z; sum.w += p.w;
            }
            float* dst = (layer == 0) ? (g_H0 + (s + 1) * HB)
                       : (layer == 1) ? (g_H1 + (s - 1) * HB)
                                      : (g_H2 + (s - 2) * HB);
            *(float4*)&dst[b * 1024 + nbase + nl4] = make_float4(
                rnd_tf32(tanhf(sum.x)), rnd_tf32(tanhf(sum.y)),
                rnd_tf32(tanhf(sum.z)), rnd_tf32(tanhf(sum.w)));
        }
        gbar(2 * s + 1, nblk);
    }
}

// out[l][b][i] = sum_h hs[b][h]*Wo[i][h] + bo[i]
__global__ void __launch_bounds__(256) out_kernel(const float* __restrict__ Wo,
                                                  const float* __restrict__ bo,
                                                  float* __restrict__ out) {
    __shared__ float Hs[64][65];
    __shared__ float Wos[32][65];
    const int l = blockIdx.y, ibase = blockIdx.x * 32;
    const float* hsrc = (l == 0) ? g_H0 + 256 * HB : (l == 1) ? g_H1 + 255 * HB : g_H2 + 255 * HB;
    const int tid = threadIdx.x, i = tid & 31, brow = tid >> 5;
    float acc[8];
#pragma unroll
    for (int q = 0; q < 8; q++) acc[q] = 0.f;
    for (int kc = 0; kc < 1024; kc += 64) {
        __syncthreads();
#pragma unroll
        for (int j = 0; j < 16; j++) {
            int e = j * 256 + tid, b = e >> 6, k = e & 63;
            Hs[b][k] = hsrc[b * 1024 + kc + k];
        }
#pragma unroll
        for (int j = 0; j < 8; j++) {
            int e = j * 256 + tid, ii = e >> 6, k = e & 63;
            Wos[ii][k] = Wo[(ibase + ii) * 1024 + kc + k];
        }
        __syncthreads();
#pragma unroll
        for (int k = 0; k < 64; k++) {
            float w = Wos[i][k];
#pragma unroll
            for (int bb = 0; bb < 8; bb++) acc[bb] += Hs[bb * 8 + brow][k] * w;
        }
    }
    float bv = bo[ibase + i];
#pragma unroll
    for (int bb = 0; bb < 8; bb++)
        out[l * 32768 + (bb * 8 + brow) * 512 + ibase + i] = acc[bb] + bv;
}

extern "C" void kernel_launch(void* const* d_in, const int* in_sizes, int n_in,
                              void* d_out, int out_size) {
    const float* x     = (const float*)d_in[0];
    const float* noise = (const float*)d_in[1];
    const float* Wi0   = (const float*)d_in[2];
    const float* Wi12  = (const float*)d_in[3];
    const float* bi    = (const float*)d_in[4];
    const float* Ws    = (const float*)d_in[5];
    const float* bs    = (const float*)d_in[6];
    const float* Wh    = (const float*)d_in[7];
    const float* bh    = (const float*)d_in[8];
    const float* Wo    = (const float*)d_in[9];
    const float* bo    = (const float*)d_in[10];
    float* out = (float*)d_out;

    int dev = 0, nblk = 148;
    cudaGetDevice(&dev);
    cudaDeviceGetAttribute(&nblk, cudaDevAttrMultiProcessorCount, dev);
    if (nblk > 296) nblk = 296;
    if (nblk < 1) nblk = 1;

    prep_kernel<<<512, 256>>>(Wi0, Wi12, bi, Ws, bs, Wh, bh, noise);
    gemmA_kernel<<<dim3(8, 256, 3), 128>>>(x);
    persist_kernel<<<nblk, 256>>>(nblk);
    out_kernel<<<dim3(16, 3), 256>>>(Wo, bo, out);
}

// round 9
// speedup vs baseline: 2.1132x; 1.0172x over previous
#include <cuda_runtime.h>
#include <math.h>

#define HB 65536   // H*B floats per t-slab
#define NU 2560    // 16-k-row units: L0 8 tiles x 64u, L1 8 x 128u, L2 8 x 128u
#define PAD 20     // smem row stride 80B: 16B-aligned float4 stores, conflict-free reads

// ---- scratch ----
__device__ float g_WrA[3072 * 512];       // tf32 [j][k]: j<1024 Wi0+Ws0, <2048 Ws1, else Ws2
__device__ float g_Wr0[1024 * 1024];      // tf32 [n][k]  (Wh0)
__device__ float g_Wr1[1024 * 2048];      // [n][k] k<1024: Wi12[0], else Wh1
__device__ float g_Wr2[1024 * 2048];      // [n][k] k<1024: Wi12[1], else Wh2
__device__ float g_b0[1024], g_b1[1024], g_b2[1024];
__device__ float g_Xh[3 * 256 * 64 * 512];  // x-combination hi (tf32) [l][t][b][k]
__device__ float g_Xl[3 * 256 * 64 * 512];  // x-combination lo (tf32)
__device__ float g_A0[256 * HB], g_A1[256 * HB], g_A2[256 * HB];  // [t][b][h] fp32
__device__ float g_H0[257 * HB];          // [i][b][h]: H0[i]=h0[i-1] (tf32-rounded)
__device__ float g_H1[256 * HB];
__device__ float g_H2[256 * HB];
__device__ float g_P[320 * 2 * 8192];     // partials [blk][seg][b(64)][n(128)]
__device__ unsigned g_bar[516];

__device__ __forceinline__ float rnd_tf32(float x) {
    unsigned r;
    asm("cvt.rna.tf32.f32 %0, %1;" : "=r"(r) : "f"(x));
    return __uint_as_float(r);
}
__device__ __forceinline__ int ustart(int b, int nblk) {
    return (int)(((long long)b * NU) / nblk);
}

__global__ void prep_kernel(const float* __restrict__ Wi0, const float* __restrict__ Wi12,
                            const float* __restrict__ bi,  const float* __restrict__ Ws,
                            const float* __restrict__ bs,  const float* __restrict__ Wh,
                            const float* __restrict__ bh,  const float* __restrict__ noise) {
    int tid = blockIdx.x * blockDim.x + threadIdx.x, nthr = gridDim.x * blockDim.x;
    for (int i = tid; i < 3072 * 512; i += nthr) {
        int j = i >> 9, k = i & 511;
        float v;
        if (j < 1024)      v = Wi0[j * 512 + k] + Ws[j * 512 + k];
        else if (j < 2048) v = Ws[524288 + (j - 1024) * 512 + k];
        else               v = Ws[1048576 + (j - 2048) * 512 + k];
        g_WrA[i] = rnd_tf32(v);
    }
    for (int i = tid; i < 1024 * 1024; i += nthr)
        g_Wr0[i] = rnd_tf32(Wh[i]);
    for (int i = tid; i < 1024 * 2048; i += nthr) {
        int n = i >> 11, k = i & 2047;
        g_Wr1[i] = rnd_tf32((k < 1024) ? Wi12[n * 1024 + k] : Wh[1048576 + n * 1024 + (k - 1024)]);
        g_Wr2[i] = rnd_tf32((k < 1024) ? Wi12[1048576 + n * 1024 + k] : Wh[2097152 + n * 1024 + (k - 1024)]);
    }
    for (int i = tid; i < 1024; i += nthr) {
        g_b0[i] = bi[i] + bs[i] + bh[i];
        g_b1[i] = bi[1024 + i] + bs[1024 + i] + bh[1024 + i];
        g_b2[i] = bi[2048 + i] + bs[2048 + i] + bh[2048 + i];
    }
    for (int i = tid; i < 516; i += nthr) g_bar[i] = 0u;
    for (int i = tid; i < HB; i += nthr) {
        g_H0[i] = rnd_tf32(noise[i]);
        g_H1[i] = rnd_tf32(noise[3 * HB + i]);
        g_H2[2 * HB + i] = rnd_tf32(noise[6 * HB + i]);
    }
}

// xcomb: build shifted/scaled x combinations, split into tf32 hi+lo
__global__ void __launch_bounds__(256) xcomb_kernel(const float* __restrict__ x) {
    int idx = blockIdx.x * blockDim.x + threadIdx.x;   // over 3*256*64*128 float4s
    if (idx >= 3 * 256 * 64 * 128) return;
    int l = idx / 2097152, rem = idx % 2097152;
    int t = rem >> 13, rem2 = rem & 8191;
    int b = rem2 >> 7, k4 = (rem2 & 127) * 4;
    const float* xb = x + b * 131072 + k4;
    float4 v = make_float4(0.f, 0.f, 0.f, 0.f);
    if (l == 0) {
        if (t + 3 < 256) v = *(const float4*)&xb[(t + 3) * 512];
    } else if (l == 1) {
        if (t + 2 < 256) { float4 u = *(const float4*)&xb[(t + 2) * 512]; v.x += u.x; v.y += u.y; v.z += u.z; v.w += u.w; }
        if (t + 3 < 256) { float4 u = *(const float4*)&xb[(t + 3) * 512]; v.x += u.x; v.y += u.y; v.z += u.z; v.w += u.w; }
        v.x *= 0.5f; v.y *= 0.5f; v.z *= 0.5f; v.w *= 0.5f;
    } else {
#pragma unroll
        for (int dt = 0; dt < 4; dt++)
            if (t + dt < 256) { float4 u = *(const float4*)&xb[(t + dt) * 512]; v.x += u.x; v.y += u.y; v.z += u.z; v.w += u.w; }
        v.x *= 0.25f; v.y *= 0.25f; v.z *= 0.25f; v.w *= 0.25f;
    }
    float4 hi = make_float4(rnd_tf32(v.x), rnd_tf32(v.y), rnd_tf32(v.z), rnd_tf32(v.w));
    float4 lo = make_float4(rnd_tf32(v.x - hi.x), rnd_tf32(v.y - hi.y),
                            rnd_tf32(v.z - hi.z), rnd_tf32(v.w - hi.w));
    int base = ((l * 16384) + t * 64 + b) * 512 + k4;
    *(float4*)&g_Xh[base] = hi;
    *(float4*)&g_Xl[base] = lo;
}

#define MMA_TF32(d, a, b) \
    asm volatile("mma.sync.aligned.m16n8k8.row.col.f32.tf32.tf32.f32 " \
                 "{%0,%1,%2,%3},{%4,%5,%6,%7},{%8,%9},{%0,%1,%2,%3};" \
                 : "+f"(d[0]), "+f"(d[1]), "+f"(d[2]), "+f"(d[3]) \
                 : "r"(a[0]), "r"(a[1]), "r"(a[2]), "r"(a[3]), "r"(b[0]), "r"(b[1]))

// A_l[t][b][h] = xc_l[t] @ WrA^T + bias_l  via tf32 mma, 2-term x-split
__global__ void __launch_bounds__(256) gemmA_mma_kernel() {
    __shared__ float Bs[128][PAD];
    __shared__ float Ah[64][PAD];
    __shared__ float Al[64][PAD];
    const int tid = threadIdx.x;
    const int warp = tid >> 5, lane = tid & 31;
    const int gid = lane >> 2, tig = lane & 3;
    const int hbase = blockIdx.x * 128, t = blockIdx.y, l = blockIdx.z;

    const int brow = tid >> 1, bhalf = tid & 1;
    const int arow = tid >> 2, aq = tid & 3;
    const float* bsrcT = g_WrA + (l * 1024 + hbase + brow) * 512 + bhalf * 8;
    const int xoff = ((l * 16384) + t * 64 + arow) * 512 + aq * 4;
    const float* xh = g_Xh + xoff;
    const float* xl = g_Xl + xoff;

    float acc[4][2][4];
#pragma unroll
    for (int mi = 0; mi < 4; mi++)
#pragma unroll
        for (int nj = 0; nj < 2; nj++)
#pragma unroll
            for (int q = 0; q < 4; q++) acc[mi][nj][q] = 0.f;

    float4 br0 = *(const float4*)(bsrcT);
    float4 br1 = *(const float4*)(bsrcT + 4);
    float4 ahv = *(const float4*)(xh);
    float4 alv = *(const float4*)(xl);
    for (int step = 0; step < 32; step++) {
        __syncthreads();
        *(float4*)&Bs[brow][bhalf * 8]     = br0;
        *(float4*)&Bs[brow][bhalf * 8 + 4] = br1;
        *(float4*)&Ah[arow][aq * 4]        = ahv;
        *(float4*)&Al[arow][aq * 4]        = alv;
        __syncthreads();
        if (step < 31) {
            int kn = (step + 1) * 16;
            br0 = *(const float4*)(bsrcT + kn);
            br1 = *(const float4*)(bsrcT + kn + 4);
            ahv = *(const float4*)(xh + kn);
            alv = *(const float4*)(xl + kn);
        }
#pragma unroll
        for (int sub = 0; sub < 2; sub++) {
            int ko = sub * 8 + tig;
            unsigned a[4][4], b[2][2];
#pragma unroll
            for (int nj = 0; nj < 2; nj++) {
                int n0 = warp * 16 + nj * 8 + gid;
                b[nj][0] = __float_as_uint(Bs[n0][ko]);
                b[nj][1] = __float_as_uint(Bs[n0][ko + 4]);
            }
#pragma unroll
            for (int mi = 0; mi < 4; mi++) {
                int r0 = mi * 16 + gid;
                a[mi][0] = __float_as_uint(Ah[r0][ko]);
                a[mi][1] = __float_as_uint(Ah[r0 + 8][ko]);
                a[mi][2] = __float_as_uint(Ah[r0][ko + 4]);
                a[mi][3] = __float_as_uint(Ah[r0 + 8][ko + 4]);
            }
#pragma unroll
            for (int mi = 0; mi < 4; mi++)
#pragma unroll
                for (int nj = 0; nj < 2; nj++) MMA_TF32(acc[mi][nj], a[mi], b[nj]);
#pragma unroll
            for (int mi = 0; mi < 4; mi++) {
                int r0 = mi * 16 + gid;
                a[mi][0] = __float_as_uint(Al[r0][ko]);
                a[mi][1] = __float_as_uint(Al[r0 + 8][ko]);
                a[mi][2] = __float_as_uint(Al[r0][ko + 4]);
                a[mi][3] = __float_as_uint(Al[r0 + 8][ko + 4]);
            }
#pragma unroll
            for (int mi = 0; mi < 4; mi++)
#pragma unroll
                for (int nj = 0; nj < 2; nj++) MMA_TF32(acc[mi][nj], a[mi], b[nj]);
        }
    }
    float* A = (l == 0) ? g_A0 : (l == 1) ? g_A1 : g_A2;
    const float* bl = (l == 0) ? g_b0 : (l == 1) ? g_b1 : g_b2;
#pragma unroll
    for (int mi = 0; mi < 4; mi++)
#pragma unroll
        for (int nj = 0; nj < 2; nj++) {
            int h = hbase + warp * 16 + nj * 8 + 2 * tig;
            float bv0 = bl[h], bv1 = bl[h + 1];
            int r = mi * 16 + gid;
            *(float2*)&A[t * HB + r * 1024 + h] =
                make_float2(acc[mi][nj][0] + bv0, acc[mi][nj][1] + bv1);
            *(float2*)&A[t * HB + (r + 8) * 1024 + h] =
                make_float2(acc[mi][nj][2] + bv0, acc[mi][nj][3] + bv1);
        }
}

__device__ __forceinline__ void gbar(int i, int nblk) {
    __syncthreads();
    if (threadIdx.x == 0) {
        __threadfence();
        atomicAdd(&g_bar[i], 1u);
        while (*((volatile unsigned*)&g_bar[i]) < (unsigned)nblk) __nanosleep(64);
        __threadfence();
    }
    __syncthreads();
}

__device__ __forceinline__ void tile_of(int u, int& layer, int& ntile, int& kst, int& tend) {
    if (u < 512)       { layer = 0; ntile = u >> 6; kst = (u & 63) * 16; tend = (ntile + 1) * 64; }
    else if (u < 1536) { int r = u - 512;  layer = 1; ntile = r >> 7; kst = (r & 127) * 16; tend = 512 + (ntile + 1) * 128; }
    else               { int r = u - 1536; layer = 2; ntile = r >> 7; kst = (r & 127) * 16; tend = 1536 + (ntile + 1) * 128; }
}

__global__ void __launch_bounds__(256) persist_kernel(int nblk) {
    __shared__ float Bs[128][PAD];
    __shared__ float As[64][PAD];
    __shared__ int tblP[24][24];
    __shared__ int tblCnt[24];
    const int tid = threadIdx.x, bid = blockIdx.x;
    const int warp = tid >> 5, lane = tid & 31;
    const int gid = lane >> 2, tig = lane & 3;
    const int u0 = ustart(bid, nblk), u1 = ustart(bid + 1, nblk);

    if (tid < 24) {
        int g = tid, t0, t1;
        if (g < 8)       { t0 = g * 64;                t1 = t0 + 64; }
        else if (g < 16) { t0 = 512 + (g - 8) * 128;   t1 = t0 + 128; }
        else             { t0 = 1536 + (g - 16) * 128; t1 = t0 + 128; }
        int cnt = 0;
        for (int bb = 0; bb < nblk; bb++) {
            int s0 = ustart(bb, nblk), s1 = ustart(bb + 1, nblk);
            if (s0 < t1 && s1 > t0) {
                int seg = (s0 < t0) ? 1 : 0;
                tblP[g][cnt++] = (bb * 2 + seg) * 8192;
            }
        }
        tblCnt[g] = cnt;
    }
    __syncthreads();

    for (int s = 0; s < 258; s++) {
        int u = u0, seg = 0;
        while (u < u1) {
            int layer, ntile, kst, tend;
            tile_of(u, layer, ntile, kst, tend);
            int uend = (u1 < tend) ? u1 : tend;
            int klen = (uend - u) * 16;
            bool valid = (layer == 0) ? (s <= 255)
                       : (layer == 1) ? (s >= 2 && s <= 256)
                                      : (s >= 5 && s <= 257);
            if (valid) {
                const int nbase = ntile * 128;
                const float* wsrc; int K;
                if (layer == 0)      { wsrc = g_Wr0; K = 1024; }
                else if (layer == 1) { wsrc = g_Wr1; K = 2048; }
                else                 { wsrc = g_Wr2; K = 2048; }
                const float *hA, *hB = 0;
                if (layer == 0)      { hA = g_H0 + s * HB; }
                else if (layer == 1) { hA = g_H0 + s * HB;       hB = g_H1 + (s - 2) * HB; }
                else                 { hA = g_H1 + (s - 2) * HB; hB = g_H2 + (s - 3) * HB; }

                const int brow = tid >> 1, bhalf = tid & 1;
                const int arow = tid >> 2, aq = tid & 3;
                const float* bsrcT = wsrc + (nbase + brow) * K + bhalf * 8;

                float acc[4][2][4];
#pragma unroll
                for (int mi = 0; mi < 4; mi++)
#pragma unroll
                    for (int nj = 0; nj < 2; nj++)
#pragma unroll
                        for (int q = 0; q < 4; q++) acc[mi][nj][q] = 0.f;

                int steps = klen >> 4;
                int kcur = kst;
                float4 br0 = *(const float4*)(bsrcT + kcur);
                float4 br1 = *(const float4*)(bsrcT + kcur + 4);
                int kg = kcur + aq * 4;
                float4 arv = (layer == 0 || kg < 1024)
                           ? *(const float4*)(hA + arow * 1024 + kg)
                           : *(const float4*)(hB + arow * 1024 + kg - 1024);
                for (int step = 0; step < steps; step++) {
                    __syncthreads();
                    *(float4*)&Bs[brow][bhalf * 8]     = br0;
                    *(float4*)&Bs[brow][bhalf * 8 + 4] = br1;
                    *(float4*)&As[arow][aq * 4]        = arv;
                    __syncthreads();
                    if (step + 1 < steps) {
                        int kn = kcur + 16;
                        br0 = *(const float4*)(bsrcT + kn);
                        br1 = *(const float4*)(bsrcT + kn + 4);
                        int kg2 = kn + aq * 4;
                        arv = (layer == 0 || kg2 < 1024)
                            ? *(const float4*)(hA + arow * 1024 + kg2)
                            : *(const float4*)(hB + arow * 1024 + kg2 - 1024);
                    }
#pragma unroll
                    for (int sub = 0; sub < 2; sub++) {
                        int ko = sub * 8 + tig;
                        unsigned a[4][4], b[2][2];
#pragma unroll
                        for (int mi = 0; mi < 4; mi++) {
                            int r0 = mi * 16 + gid;
                            a[mi][0] = __float_as_uint(As[r0][ko]);
                            a[mi][1] = __float_as_uint(As[r0 + 8][ko]);
                            a[mi][2] = __float_as_uint(As[r0][ko + 4]);
                            a[mi][3] = __float_as_uint(As[r0 + 8][ko + 4]);
                        }
#pragma unroll
                        for (int nj = 0; nj < 2; nj++) {
                            int n0 = warp * 16 + nj * 8 + gid;
                            b[nj][0] = __float_as_uint(Bs[n0][ko]);
                            b[nj][1] = __float_as_uint(Bs[n0][ko + 4]);
                        }
#pragma unroll
                        for (int mi = 0; mi < 4; mi++)
#pragma unroll
                            for (int nj = 0; nj < 2; nj++) MMA_TF32(acc[mi][nj], a[mi], b[nj]);
                    }
                    kcur += 16;
                }
                float* pb = g_P + (bid * 2 + seg) * 8192;
#pragma unroll
                for (int mi = 0; mi < 4; mi++)
#pragma unroll
                    for (int nj = 0; nj < 2; nj++) {
                        int n = warp * 16 + nj * 8 + 2 * tig;
                        int b0 = mi * 16 + gid;
                        *(float2*)&pb[b0 * 128 + n]       = make_float2(acc[mi][nj][0], acc[mi][nj][1]);
                        *(float2*)&pb[(b0 + 8) * 128 + n] = make_float2(acc[mi][nj][2], acc[mi][nj][3]);
                    }
            }
            u = uend;
            seg++;
        }
        gbar(2 * s, nblk);

        for (int idx = bid * 256 + tid; idx < 49152; idx += nblk * 256) {
            int g = idx >> 11, e = idx & 2047;
            int layer = g >> 3, ntile = g & 7;
            bool valid = (layer == 0) ? (s <= 255)
                       : (layer == 1) ? (s >= 2 && s <= 256)
                                      : (s >= 5 && s <= 257);
            if (!valid) continue;
            int b = e >> 5, nl4 = (e & 31) * 4;
            int nbase = ntile * 128;
            const float* A = (layer == 0) ? g_A0 : (layer == 1) ? g_A1 : g_A2;
            int t = (layer == 0) ? s : (layer == 1) ? (s - 1) : (s - 2);
            float4 sum = *(const float4*)&A[t * HB + b * 1024 + nbase + nl4];
            int cnt = tblCnt[g];
            for (int j = 0; j < cnt; j++) {
                float4 p = __ldcg((const float4*)&g_P[tblP[g][j] + b * 128 + nl4]);
                sum.x += p.x; sum.y += p.y; sum.z += p.z; sum.w += p.w;
            }
            float* dst = (layer == 0) ? (g_H0 + (s + 1) * HB)
                       : (layer == 1) ? (g_H1 + (s - 1) * HB)
                                      : (g_H2 + (s - 2) * HB);
            *(float4*)&dst[b * 1024 + nbase + nl4] = make_float4(
                rnd_tf32(tanhf(sum.x)), rnd_tf32(tanhf(sum.y)),
                rnd_tf32(tanhf(sum.z)), rnd_tf32(tanhf(sum.w)));
        }
        gbar(2 * s + 1, nblk);
    }
}

// out[l][b][i] = sum_h hs[b][h]*Wo[i][h] + bo[i]
__global__ void __launch_bounds__(256) out_kernel(const float* __restrict__ Wo,
                                                  const float* __restrict__ bo,
                                                  float* __restrict__ out) {
    __shared__ float Hs[64][65];
    __shared__ float Wos[32][65];
    const int l = blockIdx.y, ibase = blockIdx.x * 32;
    const float* hsrc = (l == 0) ? g_H0 + 256 * HB : (l == 1) ? g_H1 + 255 * HB : g_H2 + 255 * HB;
    const int tid = threadIdx.x, i = tid & 31, brow = tid >> 5;
    float acc[8];
#pragma unroll
    for (int q = 0; q < 8; q++) acc[q] = 0.f;
    for (int kc = 0; kc < 1024; kc += 64) {
        __syncthreads();
#pragma unroll
        for (int j = 0; j < 16; j++) {
            int e = j * 256 + tid, b = e >> 6, k = e & 63;
            Hs[b][k] = hsrc[b * 1024 + kc + k];
        }
#pragma unroll
        for (int j = 0; j < 8; j++) {
            int e = j * 256 + tid, ii = e >> 6, k = e & 63;
            Wos[ii][k] = Wo[(ibase + ii) * 1024 + kc + k];
        }
        __syncthreads();
#pragma unroll
        for (int k = 0; k < 64; k++) {
            float w = Wos[i][k];
#pragma unroll
            for (int bb = 0; bb < 8; bb++) acc[bb] += Hs[bb * 8 + brow][k] * w;
        }
    }
    float bv = bo[ibase + i];
#pragma unroll
    for (int bb = 0; bb < 8; bb++)
        out[l * 32768 + (bb * 8 + brow) * 512 + ibase + i] = acc[bb] + bv;
}

extern "C" void kernel_launch(void* const* d_in, const int* in_sizes, int n_in,
                              void* d_out, int out_size) {
    const float* x     = (const float*)d_in[0];
    const float* noise = (const float*)d_in[1];
    const float* Wi0   = (const float*)d_in[2];
    const float* Wi12  = (const float*)d_in[3];
    const float* bi    = (const float*)d_in[4];
    const float* Ws    = (const float*)d_in[5];
    const float* bs    = (const float*)d_in[6];
    const float* Wh    = (const float*)d_in[7];
    const float* bh    = (const float*)d_in[8];
    const float* Wo    = (const float*)d_in[9];
    const float* bo    = (const float*)d_in[10];
    float* out = (float*)d_out;

    int dev = 0, nblk = 148;
    cudaGetDevice(&dev);
    cudaDeviceGetAttribute(&nblk, cudaDevAttrMultiProcessorCount, dev);
    if (nblk > 296) nblk = 296;
    if (nblk < 1) nblk = 1;

    prep_kernel<<<512, 256>>>(Wi0, Wi12, bi, Ws, bs, Wh, bh, noise);
    xcomb_kernel<<<24576, 256>>>(x);
    gemmA_mma_kernel<<<dim3(8, 256, 3), 256>>>();
    persist_kernel<<<nblk, 256>>>(nblk);
    out_kernel<<<dim3(16, 3), 256>>>(Wo, bo, out);
}

// round 10
// speedup vs baseline: 2.1487x; 1.0168x over previous
#include <cuda_runtime.h>
#include <math.h>

#define HB 65536   // H*B floats per t-slab
#define NU 2560    // 16-k-row units: L0 8 tiles x 64u, L1 8 x 128u, L2 8 x 128u
#define PAD 20     // smem row stride 80B: 16B-aligned float4 stores, conflict-free reads

// ---- scratch ----
__device__ float g_WrA[3072 * 512];       // tf32 [j][k]: j<1024 Wi0+Ws0, <2048 Ws1, else Ws2
__device__ float g_Wr0[1024 * 1024];      // tf32 [n][k]  (Wh0)
__device__ float g_Wr1[1024 * 2048];      // [n][k] k<1024: Wi12[0], else Wh1
__device__ float g_Wr2[1024 * 2048];      // [n][k] k<1024: Wi12[1], else Wh2
__device__ float g_b0[1024], g_b1[1024], g_b2[1024];
__device__ float g_Xh[3 * 256 * 64 * 512];  // x-combination hi (tf32) [l][t][b][k]
__device__ float g_Xl[3 * 256 * 64 * 512];  // x-combination lo (tf32)
__device__ float g_A0[256 * HB], g_A1[256 * HB], g_A2[256 * HB];  // [t][b][h] fp32
__device__ float g_H0[257 * HB];          // [i][b][h]: H0[i]=h0[i-1] (tf32-rounded)
__device__ float g_H1[256 * HB];
__device__ float g_H2[256 * HB];
__device__ float g_P[320 * 2 * 8192];     // partials [blk][seg][b(64)][n(128)]
__device__ unsigned g_bar[516];

__device__ __forceinline__ float rnd_tf32(float x) {
    unsigned r;
    asm("cvt.rna.tf32.f32 %0, %1;" : "=r"(r) : "f"(x));
    return __uint_as_float(r);
}
__device__ __forceinline__ int ustart(int b, int nblk) {
    return (int)(((long long)b * NU) / nblk);
}

__global__ void prep_kernel(const float* __restrict__ Wi0, const float* __restrict__ Wi12,
                            const float* __restrict__ bi,  const float* __restrict__ Ws,
                            const float* __restrict__ bs,  const float* __restrict__ Wh,
                            const float* __restrict__ bh,  const float* __restrict__ noise) {
    int tid = blockIdx.x * blockDim.x + threadIdx.x, nthr = gridDim.x * blockDim.x;
    for (int i = tid; i < 3072 * 512; i += nthr) {
        int j = i >> 9, k = i & 511;
        float v;
        if (j < 1024)      v = Wi0[j * 512 + k] + Ws[j * 512 + k];
        else if (j < 2048) v = Ws[524288 + (j - 1024) * 512 + k];
        else               v = Ws[1048576 + (j - 2048) * 512 + k];
        g_WrA[i] = rnd_tf32(v);
    }
    for (int i = tid; i < 1024 * 1024; i += nthr)
        g_Wr0[i] = rnd_tf32(Wh[i]);
    for (int i = tid; i < 1024 * 2048; i += nthr) {
        int n = i >> 11, k = i & 2047;
        g_Wr1[i] = rnd_tf32((k < 1024) ? Wi12[n * 1024 + k] : Wh[1048576 + n * 1024 + (k - 1024)]);
        g_Wr2[i] = rnd_tf32((k < 1024) ? Wi12[1048576 + n * 1024 + k] : Wh[2097152 + n * 1024 + (k - 1024)]);
    }
    for (int i = tid; i < 1024; i += nthr) {
        g_b0[i] = bi[i] + bs[i] + bh[i];
        g_b1[i] = bi[1024 + i] + bs[1024 + i] + bh[1024 + i];
        g_b2[i] = bi[2048 + i] + bs[2048 + i] + bh[2048 + i];
    }
    for (int i = tid; i < 516; i += nthr) g_bar[i] = 0u;
    for (int i = tid; i < HB; i += nthr) {
        g_H0[i] = rnd_tf32(noise[i]);
        g_H1[i] = rnd_tf32(noise[3 * HB + i]);
        g_H2[2 * HB + i] = rnd_tf32(noise[6 * HB + i]);
    }
}

// xcomb: build shifted/scaled x combinations, split into tf32 hi+lo
__global__ void __launch_bounds__(256) xcomb_kernel(const float* __restrict__ x) {
    int idx = blockIdx.x * blockDim.x + threadIdx.x;
    if (idx >= 3 * 256 * 64 * 128) return;
    int l = idx / 2097152, rem = idx % 2097152;
    int t = rem >> 13, rem2 = rem & 8191;
    int b = rem2 >> 7, k4 = (rem2 & 127) * 4;
    const float* xb = x + b * 131072 + k4;
    float4 v = make_float4(0.f, 0.f, 0.f, 0.f);
    if (l == 0) {
        if (t + 3 < 256) v = *(const float4*)&xb[(t + 3) * 512];
    } else if (l == 1) {
        if (t + 2 < 256) { float4 u = *(const float4*)&xb[(t + 2) * 512]; v.x += u.x; v.y += u.y; v.z += u.z; v.w += u.w; }
        if (t + 3 < 256) { float4 u = *(const float4*)&xb[(t + 3) * 512]; v.x += u.x; v.y += u.y; v.z += u.z; v.w += u.w; }
        v.x *= 0.5f; v.y *= 0.5f; v.z *= 0.5f; v.w *= 0.5f;
    } else {
#pragma unroll
        for (int dt = 0; dt < 4; dt++)
            if (t + dt < 256) { float4 u = *(const float4*)&xb[(t + dt) * 512]; v.x += u.x; v.y += u.y; v.z += u.z; v.w += u.w; }
        v.x *= 0.25f; v.y *= 0.25f; v.z *= 0.25f; v.w *= 0.25f;
    }
    float4 hi = make_float4(rnd_tf32(v.x), rnd_tf32(v.y), rnd_tf32(v.z), rnd_tf32(v.w));
    float4 lo = make_float4(rnd_tf32(v.x - hi.x), rnd_tf32(v.y - hi.y),
                            rnd_tf32(v.z - hi.z), rnd_tf32(v.w - hi.w));
    int base = ((l * 16384) + t * 64 + b) * 512 + k4;
    *(float4*)&g_Xh[base] = hi;
    *(float4*)&g_Xl[base] = lo;
}

#define MMA_TF32(d, a, b) \
    asm volatile("mma.sync.aligned.m16n8k8.row.col.f32.tf32.tf32.f32 " \
                 "{%0,%1,%2,%3},{%4,%5,%6,%7},{%8,%9},{%0,%1,%2,%3};" \
                 : "+f"(d[0]), "+f"(d[1]), "+f"(d[2]), "+f"(d[3]) \
                 : "r"(a[0]), "r"(a[1]), "r"(a[2]), "r"(a[3]), "r"(b[0]), "r"(b[1]))

// A_l[t][b][h] = xc_l[t] @ WrA^T + bias_l  via tf32 mma, 2-term x-split
__global__ void __launch_bounds__(256) gemmA_mma_kernel() {
    __shared__ float Bs[128][PAD];
    __shared__ float Ah[64][PAD];
    __shared__ float Al[64][PAD];
    const int tid = threadIdx.x;
    const int warp = tid >> 5, lane = tid & 31;
    const int gid = lane >> 2, tig = lane & 3;
    const int hbase = blockIdx.x * 128, t = blockIdx.y, l = blockIdx.z;

    const int brow = tid >> 1, bhalf = tid & 1;
    const int arow = tid >> 2, aq = tid & 3;
    const float* bsrcT = g_WrA + (l * 1024 + hbase + brow) * 512 + bhalf * 8;
    const int xoff = ((l * 16384) + t * 64 + arow) * 512 + aq * 4;
    const float* xh = g_Xh + xoff;
    const float* xl = g_Xl + xoff;

    float acc[4][2][4];
#pragma unroll
    for (int mi = 0; mi < 4; mi++)
#pragma unroll
        for (int nj = 0; nj < 2; nj++)
#pragma unroll
            for (int q = 0; q < 4; q++) acc[mi][nj][q] = 0.f;

    float4 br0 = *(const float4*)(bsrcT);
    float4 br1 = *(const float4*)(bsrcT + 4);
    float4 ahv = *(const float4*)(xh);
    float4 alv = *(const float4*)(xl);
    for (int step = 0; step < 32; step++) {
        __syncthreads();
        *(float4*)&Bs[brow][bhalf * 8]     = br0;
        *(float4*)&Bs[brow][bhalf * 8 + 4] = br1;
        *(float4*)&Ah[arow][aq * 4]        = ahv;
        *(float4*)&Al[arow][aq * 4]        = alv;
        __syncthreads();
        if (step < 31) {
            int kn = (step + 1) * 16;
            br0 = *(const float4*)(bsrcT + kn);
            br1 = *(const float4*)(bsrcT + kn + 4);
            ahv = *(const float4*)(xh + kn);
            alv = *(const float4*)(xl + kn);
        }
#pragma unroll
        for (int sub = 0; sub < 2; sub++) {
            int ko = sub * 8 + tig;
            unsigned a[4][4], b[2][2];
#pragma unroll
            for (int nj = 0; nj < 2; nj++) {
                int n0 = warp * 16 + nj * 8 + gid;
                b[nj][0] = __float_as_uint(Bs[n0][ko]);
                b[nj][1] = __float_as_uint(Bs[n0][ko + 4]);
            }
#pragma unroll
            for (int mi = 0; mi < 4; mi++) {
                int r0 = mi * 16 + gid;
                a[mi][0] = __float_as_uint(Ah[r0][ko]);
                a[mi][1] = __float_as_uint(Ah[r0 + 8][ko]);
                a[mi][2] = __float_as_uint(Ah[r0][ko + 4]);
                a[mi][3] = __float_as_uint(Ah[r0 + 8][ko + 4]);
            }
#pragma unroll
            for (int mi = 0; mi < 4; mi++)
#pragma unroll
                for (int nj = 0; nj < 2; nj++) MMA_TF32(acc[mi][nj], a[mi], b[nj]);
#pragma unroll
            for (int mi = 0; mi < 4; mi++) {
                int r0 = mi * 16 + gid;
                a[mi][0] = __float_as_uint(Al[r0][ko]);
                a[mi][1] = __float_as_uint(Al[r0 + 8][ko]);
                a[mi][2] = __float_as_uint(Al[r0][ko + 4]);
                a[mi][3] = __float_as_uint(Al[r0 + 8][ko + 4]);
            }
#pragma unroll
            for (int mi = 0; mi < 4; mi++)
#pragma unroll
                for (int nj = 0; nj < 2; nj++) MMA_TF32(acc[mi][nj], a[mi], b[nj]);
        }
    }
    float* A = (l == 0) ? g_A0 : (l == 1) ? g_A1 : g_A2;
    const float* bl = (l == 0) ? g_b0 : (l == 1) ? g_b1 : g_b2;
#pragma unroll
    for (int mi = 0; mi < 4; mi++)
#pragma unroll
        for (int nj = 0; nj < 2; nj++) {
            int h = hbase + warp * 16 + nj * 8 + 2 * tig;
            float bv0 = bl[h], bv1 = bl[h + 1];
            int r = mi * 16 + gid;
            *(float2*)&A[t * HB + r * 1024 + h] =
                make_float2(acc[mi][nj][0] + bv0, acc[mi][nj][1] + bv1);
            *(float2*)&A[t * HB + (r + 8) * 1024 + h] =
                make_float2(acc[mi][nj][2] + bv0, acc[mi][nj][3] + bv1);
        }
}

__device__ __forceinline__ void gbar(int i, int nblk) {
    __syncthreads();
    if (threadIdx.x == 0) {
        __threadfence();
        atomicAdd(&g_bar[i], 1u);
        while (*((volatile unsigned*)&g_bar[i]) < (unsigned)nblk) __nanosleep(32);
        __threadfence();
    }
    __syncthreads();
}

__device__ __forceinline__ void tile_of(int u, int& layer, int& ntile, int& kst, int& tend) {
    if (u < 512)       { layer = 0; ntile = u >> 6; kst = (u & 63) * 16; tend = (ntile + 1) * 64; }
    else if (u < 1536) { int r = u - 512;  layer = 1; ntile = r >> 7; kst = (r & 127) * 16; tend = 512 + (ntile + 1) * 128; }
    else               { int r = u - 1536; layer = 2; ntile = r >> 7; kst = (r & 127) * 16; tend = 1536 + (ntile + 1) * 128; }
}

__global__ void __launch_bounds__(256) persist_kernel(int nblk) {
    __shared__ float Bs[2][128][PAD];
    __shared__ float As[2][64][PAD];
    __shared__ int tblP[24][24];
    __shared__ int tblCnt[24];
    const int tid = threadIdx.x, bid = blockIdx.x;
    const int warp = tid >> 5, lane = tid & 31;
    const int gid = lane >> 2, tig = lane & 3;
    const int u0 = ustart(bid, nblk), u1 = ustart(bid + 1, nblk);

    if (tid < 24) {
        int g = tid, t0, t1;
        if (g < 8)       { t0 = g * 64;                t1 = t0 + 64; }
        else if (g < 16) { t0 = 512 + (g - 8) * 128;   t1 = t0 + 128; }
        else             { t0 = 1536 + (g - 16) * 128; t1 = t0 + 128; }
        int cnt = 0;
        for (int bb = 0; bb < nblk; bb++) {
            int s0 = ustart(bb, nblk), s1 = ustart(bb + 1, nblk);
            if (s0 < t1 && s1 > t0) {
                int seg = (s0 < t0) ? 1 : 0;
                tblP[g][cnt++] = (bb * 2 + seg) * 8192;
            }
        }
        tblCnt[g] = cnt;
    }
    __syncthreads();

    int pp = 0;   // smem staging parity (carried across steps/tiles/slots)
    for (int s = 0; s < 258; s++) {
        int u = u0, seg = 0;
        while (u < u1) {
            int layer, ntile, kst, tend;
            tile_of(u, layer, ntile, kst, tend);
            int uend = (u1 < tend) ? u1 : tend;
            int klen = (uend - u) * 16;
            bool valid = (layer == 0) ? (s <= 255)
                       : (layer == 1) ? (s >= 2 && s <= 256)
                                      : (s >= 5 && s <= 257);
            if (valid) {
                const int nbase = ntile * 128;
                const float* wsrc; int K;
                if (layer == 0)      { wsrc = g_Wr0; K = 1024; }
                else if (layer == 1) { wsrc = g_Wr1; K = 2048; }
                else                 { wsrc = g_Wr2; K = 2048; }
                const float *hA, *hB = 0;
                if (layer == 0)      { hA = g_H0 + s * HB; }
                else if (layer == 1) { hA = g_H0 + s * HB;       hB = g_H1 + (s - 2) * HB; }
                else                 { hA = g_H1 + (s - 2) * HB; hB = g_H2 + (s - 3) * HB; }

                const int brow = tid >> 1, bhalf = tid & 1;
                const int arow = tid >> 2, aq = tid & 3;
                const float* bsrcT = wsrc + (nbase + brow) * K + bhalf * 8;

                float acc[4][2][4];
#pragma unroll
                for (int mi = 0; mi < 4; mi++)
#pragma unroll
                    for (int nj = 0; nj < 2; nj++)
#pragma unroll
                        for (int q = 0; q < 4; q++) acc[mi][nj][q] = 0.f;

                int steps = klen >> 4;
                int kcur = kst;
                float4 br0 = *(const float4*)(bsrcT + kcur);
                float4 br1 = *(const float4*)(bsrcT + kcur + 4);
                int kg = kcur + aq * 4;
                float4 arv = (layer == 0 || kg < 1024)
                           ? *(const float4*)(hA + arow * 1024 + kg)
                           : *(const float4*)(hB + arow * 1024 + kg - 1024);
                for (int step = 0; step < steps; step++) {
                    *(float4*)&Bs[pp][brow][bhalf * 8]     = br0;
                    *(float4*)&Bs[pp][brow][bhalf * 8 + 4] = br1;
                    *(float4*)&As[pp][arow][aq * 4]        = arv;
                    __syncthreads();
                    if (step + 1 < steps) {
                        int kn = kcur + 16;
                        br0 = *(const float4*)(bsrcT + kn);
                        br1 = *(const float4*)(bsrcT + kn + 4);
                        int kg2 = kn + aq * 4;
                        arv = (layer == 0 || kg2 < 1024)
                            ? *(const float4*)(hA + arow * 1024 + kg2)
                            : *(const float4*)(hB + arow * 1024 + kg2 - 1024);
                    }
#pragma unroll
                    for (int sub = 0; sub < 2; sub++) {
                        int ko = sub * 8 + tig;
                        unsigned a[4][4], b[2][2];
#pragma unroll
                        for (int mi = 0; mi < 4; mi++) {
                            int r0 = mi * 16 + gid;
                            a[mi][0] = __float_as_uint(As[pp][r0][ko]);
                            a[mi][1] = __float_as_uint(As[pp][r0 + 8][ko]);
                            a[mi][2] = __float_as_uint(As[pp][r0][ko + 4]);
                            a[mi][3] = __float_as_uint(As[pp][r0 + 8][ko + 4]);
                        }
#pragma unroll
                        for (int nj = 0; nj < 2; nj++) {
                            int n0 = warp * 16 + nj * 8 + gid;
                            b[nj][0] = __float_as_uint(Bs[pp][n0][ko]);
                            b[nj][1] = __float_as_uint(Bs[pp][n0][ko + 4]);
                        }
#pragma unroll
                        for (int mi = 0; mi < 4; mi++)
#pragma unroll
                            for (int nj = 0; nj < 2; nj++) MMA_TF32(acc[mi][nj], a[mi], b[nj]);
                    }
                    kcur += 16;
                    pp ^= 1;
                }
                float* pb = g_P + (bid * 2 + seg) * 8192;
#pragma unroll
                for (int mi = 0; mi < 4; mi++)
#pragma unroll
                    for (int nj = 0; nj < 2; nj++) {
                        int n = warp * 16 + nj * 8 + 2 * tig;
                        int b0 = mi * 16 + gid;
                        *(float2*)&pb[b0 * 128 + n]       = make_float2(acc[mi][nj][0], acc[mi][nj][1]);
                        *(float2*)&pb[(b0 + 8) * 128 + n] = make_float2(acc[mi][nj][2], acc[mi][nj][3]);
                    }
            }
            u = uend;
            seg++;
        }
        gbar(2 * s, nblk);

        for (int idx = bid * 256 + tid; idx < 49152; idx += nblk * 256) {
            int g = idx >> 11, e = idx & 2047;
            int layer = g >> 3, ntile = g & 7;
            bool valid = (layer == 0) ? (s <= 255)
                       : (layer == 1) ? (s >= 2 && s <= 256)
                                      : (s >= 5 && s <= 257);
            if (!valid) continue;
            int b = e >> 5, nl4 = (e & 31) * 4;
            int nbase = ntile * 128;
            const float* A = (layer == 0) ? g_A0 : (layer == 1) ? g_A1 : g_A2;
            int t = (layer == 0) ? s : (layer == 1) ? (s - 1) : (s - 2);
            float4 sum = *(const float4*)&A[t * HB + b * 1024 + nbase + nl4];
            int cnt = tblCnt[g];
            for (int j = 0; j < cnt; j++) {
                float4 p = __ldcg((const float4*)&g_P[tblP[g][j] + b * 128 + nl4]);
                sum.x += p.x; sum.y += p.y; sum.z += p.z; sum.w += p.w;
            }
            float* dst = (layer == 0) ? (g_H0 + (s + 1) * HB)
                       : (layer == 1) ? (g_H1 + (s - 1) * HB)
                                      : (g_H2 + (s - 2) * HB);
            *(float4*)&dst[b * 1024 + nbase + nl4] = make_float4(
                rnd_tf32(tanhf(sum.x)), rnd_tf32(tanhf(sum.y)),
                rnd_tf32(tanhf(sum.z)), rnd_tf32(tanhf(sum.w)));
        }
        gbar(2 * s + 1, nblk);
    }
}

// out[l][b][i] = sum_h hs[b][h]*Wo[i][h] + bo[i]
__global__ void __launch_bounds__(256) out_kernel(const float* __restrict__ Wo,
                                                  const float* __restrict__ bo,
                                                  float* __restrict__ out) {
    __shared__ float Hs[64][65];
    __shared__ float Wos[32][65];
    const int l = blockIdx.y, ibase = blockIdx.x * 32;
    const float* hsrc = (l == 0) ? g_H0 + 256 * HB : (l == 1) ? g_H1 + 255 * HB : g_H2 + 255 * HB;
    const int tid = threadIdx.x, i = tid & 31, brow = tid >> 5;
    float acc[8];
#pragma unroll
    for (int q = 0; q < 8; q++) acc[q] = 0.f;
    for (int kc = 0; kc < 1024; kc += 64) {
        __syncthreads();
#pragma unroll
        for (int j = 0; j < 16; j++) {
            int e = j * 256 + tid, b = e >> 6, k = e & 63;
            Hs[b][k] = hsrc[b * 1024 + kc + k];
        }
#pragma unroll
        for (int j = 0; j < 8; j++) {
            int e = j * 256 + tid, ii = e >> 6, k = e & 63;
            Wos[ii][k] = Wo[(ibase + ii) * 1024 + kc + k];
        }
        __syncthreads();
#pragma unroll
        for (int k = 0; k < 64; k++) {
            float w = Wos[i][k];
#pragma unroll
            for (int bb = 0; bb < 8; bb++) acc[bb] += Hs[bb * 8 + brow][k] * w;
        }
    }
    float bv = bo[ibase + i];
#pragma unroll
    for (int bb = 0; bb < 8; bb++)
        out[l * 32768 + (bb * 8 + brow) * 512 + ibase + i] = acc[bb] + bv;
}

extern "C" void kernel_launch(void* const* d_in, const int* in_sizes, int n_in,
                              void* d_out, int out_size) {
    const float* x     = (const float*)d_in[0];
    const float* noise = (const float*)d_in[1];
    const float* Wi0   = (const float*)d_in[2];
    const float* Wi12  = (const float*)d_in[3];
    const float* bi    = (const float*)d_in[4];
    const float* Ws    = (const float*)d_in[5];
    const float* bs    = (const float*)d_in[6];
    const float* Wh    = (const float*)d_in[7];
    const float* bh    = (const float*)d_in[8];
    const float* Wo    = (const float*)d_in[9];
    const float* bo    = (const float*)d_in[10];
    float* out = (float*)d_out;

    int dev = 0, sm = 148;
    cudaGetDevice(&dev);
    cudaDeviceGetAttribute(&sm, cudaDevAttrMultiProcessorCount, dev);
    int occ = 1;
    cudaOccupancyMaxActiveBlocksPerMultiprocessor(&occ, persist_kernel, 256, 0);
    if (occ < 1) occ = 1;
    if (occ > 2) occ = 2;
    int nblk = sm * occ;
    if (nblk > 296) nblk = 296;
    if (nblk < 1) nblk = 1;

    prep_kernel<<<512, 256>>>(Wi0, Wi12, bi, Ws, bs, Wh, bh, noise);
    xcomb_kernel<<<24576, 256>>>(x);
    gemmA_mma_kernel<<<dim3(8, 256, 3), 256>>>();
    persist_kernel<<<nblk, 256>>>(nblk);
    out_kernel<<<dim3(16, 3), 256>>>(Wo, bo, out);
}

// round 11
// speedup vs baseline: 2.3286x; 1.0837x over previous
#include <cuda_runtime.h>
#include <math.h>

#define HB 65536   // H*B floats per t-slab
#define NU 2560    // 16-k-row units: L0 8 tiles x 64u, L1 8 x 128u, L2 8 x 128u
#define PAD 20     // smem row stride 80B: 16B-aligned float4 stores, conflict-free reads
#define UFLOATS (128 * PAD)   // floats per weight unit in smem (2560)

// ---- scratch ----
__device__ float g_WrA[3072 * 512];       // tf32 [j][k]: j<1024 Wi0+Ws0, <2048 Ws1, else Ws2
__device__ float g_Wr0[1024 * 1024];      // tf32 [n][k]  (Wh0)
__device__ float g_Wr1[1024 * 2048];      // [n][k] k<1024: Wi12[0], else Wh1
__device__ float g_Wr2[1024 * 2048];      // [n][k] k<1024: Wi12[1], else Wh2
__device__ float g_b0[1024], g_b1[1024], g_b2[1024];
__device__ float g_Xh[3 * 256 * 64 * 512];  // x-combination hi (tf32) [l][t][b][k]
__device__ float g_Xl[3 * 256 * 64 * 512];  // x-combination lo (tf32)
__device__ float g_A0[256 * HB], g_A1[256 * HB], g_A2[256 * HB];  // [t][b][h] fp32
__device__ float g_H0[257 * HB];          // [i][b][h]: H0[i]=h0[i-1] (tf32-rounded)
__device__ float g_H1[256 * HB];
__device__ float g_H2[256 * HB];
__device__ float g_P[320 * 2 * 8192];     // partials [blk][seg][b(64)][n(128)]
__device__ unsigned g_bar[516];

__device__ __forceinline__ float rnd_tf32(float x) {
    unsigned r;
    asm("cvt.rna.tf32.f32 %0, %1;" : "=r"(r) : "f"(x));
    return __uint_as_float(r);
}
__device__ __forceinline__ int ustart(int b, int nblk) {
    return (int)(((long long)b * NU) / nblk);
}

__global__ void prep_kernel(const float* __restrict__ Wi0, const float* __restrict__ Wi12,
                            const float* __restrict__ bi,  const float* __restrict__ Ws,
                            const float* __restrict__ bs,  const float* __restrict__ Wh,
                            const float* __restrict__ bh,  const float* __restrict__ noise) {
    int tid = blockIdx.x * blockDim.x + threadIdx.x, nthr = gridDim.x * blockDim.x;
    for (int i = tid; i < 3072 * 512; i += nthr) {
        int j = i >> 9, k = i & 511;
        float v;
        if (j < 1024)      v = Wi0[j * 512 + k] + Ws[j * 512 + k];
        else if (j < 2048) v = Ws[524288 + (j - 1024) * 512 + k];
        else               v = Ws[1048576 + (j - 2048) * 512 + k];
        g_WrA[i] = rnd_tf32(v);
    }
    for (int i = tid; i < 1024 * 1024; i += nthr)
        g_Wr0[i] = rnd_tf32(Wh[i]);
    for (int i = tid; i < 1024 * 2048; i += nthr) {
        int n = i >> 11, k = i & 2047;
        g_Wr1[i] = rnd_tf32((k < 1024) ? Wi12[n * 1024 + k] : Wh[1048576 + n * 1024 + (k - 1024)]);
        g_Wr2[i] = rnd_tf32((k < 1024) ? Wi12[1048576 + n * 1024 + k] : Wh[2097152 + n * 1024 + (k - 1024)]);
    }
    for (int i = tid; i < 1024; i += nthr) {
        g_b0[i] = bi[i] + bs[i] + bh[i];
        g_b1[i] = bi[1024 + i] + bs[1024 + i] + bh[1024 + i];
        g_b2[i] = bi[2048 + i] + bs[2048 + i] + bh[2048 + i];
    }
    for (int i = tid; i < 516; i += nthr) g_bar[i] = 0u;
    for (int i = tid; i < HB; i += nthr) {
        g_H0[i] = rnd_tf32(noise[i]);
        g_H1[i] = rnd_tf32(noise[3 * HB + i]);
        g_H2[2 * HB + i] = rnd_tf32(noise[6 * HB + i]);
    }
}

// xcomb: build shifted/scaled x combinations, split into tf32 hi+lo
__global__ void __launch_bounds__(256) xcomb_kernel(const float* __restrict__ x) {
    int idx = blockIdx.x * blockDim.x + threadIdx.x;
    if (idx >= 3 * 256 * 64 * 128) return;
    int l = idx / 2097152, rem = idx % 2097152;
    int t = rem >> 13, rem2 = rem & 8191;
    int b = rem2 >> 7, k4 = (rem2 & 127) * 4;
    const float* xb = x + b * 131072 + k4;
    float4 v = make_float4(0.f, 0.f, 0.f, 0.f);
    if (l == 0) {
        if (t + 3 < 256) v = *(const float4*)&xb[(t + 3) * 512];
    } else if (l == 1) {
        if (t + 2 < 256) { float4 u = *(const float4*)&xb[(t + 2) * 512]; v.x += u.x; v.y += u.y; v.z += u.z; v.w += u.w; }
        if (t + 3 < 256) { float4 u = *(const float4*)&xb[(t + 3) * 512]; v.x += u.x; v.y += u.y; v.z += u.z; v.w += u.w; }
        v.x *= 0.5f; v.y *= 0.5f; v.z *= 0.5f; v.w *= 0.5f;
    } else {
#pragma unroll
        for (int dt = 0; dt < 4; dt++)
            if (t + dt < 256) { float4 u = *(const float4*)&xb[(t + dt) * 512]; v.x += u.x; v.y += u.y; v.z += u.z; v.w += u.w; }
        v.x *= 0.25f; v.y *= 0.25f; v.z *= 0.25f; v.w *= 0.25f;
    }
    float4 hi = make_float4(rnd_tf32(v.x), rnd_tf32(v.y), rnd_tf32(v.z), rnd_tf32(v.w));
    float4 lo = make_float4(rnd_tf32(v.x - hi.x), rnd_tf32(v.y - hi.y),
                            rnd_tf32(v.z - hi.z), rnd_tf32(v.w - hi.w));
    int base = ((l * 16384) + t * 64 + b) * 512 + k4;
    *(float4*)&g_Xh[base] = hi;
    *(float4*)&g_Xl[base] = lo;
}

#define MMA_TF32(d, a, b) \
    asm volatile("mma.sync.aligned.m16n8k8.row.col.f32.tf32.tf32.f32 " \
                 "{%0,%1,%2,%3},{%4,%5,%6,%7},{%8,%9},{%0,%1,%2,%3};" \
                 : "+f"(d[0]), "+f"(d[1]), "+f"(d[2]), "+f"(d[3]) \
                 : "r"(a[0]), "r"(a[1]), "r"(a[2]), "r"(a[3]), "r"(b[0]), "r"(b[1]))

// A_l[t][b][h] = xc_l[t] @ WrA^T + bias_l  via tf32 mma, 2-term x-split
__global__ void __launch_bounds__(256) gemmA_mma_kernel() {
    __shared__ float Bs[128][PAD];
    __shared__ float Ah[64][PAD];
    __shared__ float Al[64][PAD];
    const int tid = threadIdx.x;
    const int warp = tid >> 5, lane = tid & 31;
    const int gid = lane >> 2, tig = lane & 3;
    const int hbase = blockIdx.x * 128, t = blockIdx.y, l = blockIdx.z;

    const int brow = tid >> 1, bhalf = tid & 1;
    const int arow = tid >> 2, aq = tid & 3;
    const float* bsrcT = g_WrA + (l * 1024 + hbase + brow) * 512 + bhalf * 8;
    const int xoff = ((l * 16384) + t * 64 + arow) * 512 + aq * 4;
    const float* xh = g_Xh + xoff;
    const float* xl = g_Xl + xoff;

    float acc[4][2][4];
#pragma unroll
    for (int mi = 0; mi < 4; mi++)
#pragma unroll
        for (int nj = 0; nj < 2; nj++)
#pragma unroll
            for (int q = 0; q < 4; q++) acc[mi][nj][q] = 0.f;

    float4 br0 = *(const float4*)(bsrcT);
    float4 br1 = *(const float4*)(bsrcT + 4);
    float4 ahv = *(const float4*)(xh);
    float4 alv = *(const float4*)(xl);
    for (int step = 0; step < 32; step++) {
        __syncthreads();
        *(float4*)&Bs[brow][bhalf * 8]     = br0;
        *(float4*)&Bs[brow][bhalf * 8 + 4] = br1;
        *(float4*)&Ah[arow][aq * 4]        = ahv;
        *(float4*)&Al[arow][aq * 4]        = alv;
        __syncthreads();
        if (step < 31) {
            int kn = (step + 1) * 16;
            br0 = *(const float4*)(bsrcT + kn);
            br1 = *(const float4*)(bsrcT + kn + 4);
            ahv = *(const float4*)(xh + kn);
            alv = *(const float4*)(xl + kn);
        }
#pragma unroll
        for (int sub = 0; sub < 2; sub++) {
            int ko = sub * 8 + tig;
            unsigned a[4][4], b[2][2];
#pragma unroll
            for (int nj = 0; nj < 2; nj++) {
                int n0 = warp * 16 + nj * 8 + gid;
                b[nj][0] = __float_as_uint(Bs[n0][ko]);
                b[nj][1] = __float_as_uint(Bs[n0][ko + 4]);
            }
#pragma unroll
            for (int mi = 0; mi < 4; mi++) {
                int r0 = mi * 16 + gid;
                a[mi][0] = __float_as_uint(Ah[r0][ko]);
                a[mi][1] = __float_as_uint(Ah[r0 + 8][ko]);
                a[mi][2] = __float_as_uint(Ah[r0][ko + 4]);
                a[mi][3] = __float_as_uint(Ah[r0 + 8][ko + 4]);
            }
#pragma unroll
            for (int mi = 0; mi < 4; mi++)
#pragma unroll
                for (int nj = 0; nj < 2; nj++) MMA_TF32(acc[mi][nj], a[mi], b[nj]);
#pragma unroll
            for (int mi = 0; mi < 4; mi++) {
                int r0 = mi * 16 + gid;
                a[mi][0] = __float_as_uint(Al[r0][ko]);
                a[mi][1] = __float_as_uint(Al[r0 + 8][ko]);
                a[mi][2] = __float_as_uint(Al[r0][ko + 4]);
                a[mi][3] = __float_as_uint(Al[r0 + 8][ko + 4]);
            }
#pragma unroll
            for (int mi = 0; mi < 4; mi++)
#pragma unroll
                for (int nj = 0; nj < 2; nj++) MMA_TF32(acc[mi][nj], a[mi], b[nj]);
        }
    }
    float* A = (l == 0) ? g_A0 : (l == 1) ? g_A1 : g_A2;
    const float* bl = (l == 0) ? g_b0 : (l == 1) ? g_b1 : g_b2;
#pragma unroll
    for (int mi = 0; mi < 4; mi++)
#pragma unroll
        for (int nj = 0; nj < 2; nj++) {
            int h = hbase + warp * 16 + nj * 8 + 2 * tig;
            float bv0 = bl[h], bv1 = bl[h + 1];
            int r = mi * 16 + gid;
            *(float2*)&A[t * HB + r * 1024 + h] =
                make_float2(acc[mi][nj][0] + bv0, acc[mi][nj][1] + bv1);
            *(float2*)&A[t * HB + (r + 8) * 1024 + h] =
                make_float2(acc[mi][nj][2] + bv0, acc[mi][nj][3] + bv1);
        }
}

__device__ __forceinline__ void gbar(int i, int nblk) {
    __syncthreads();
    if (threadIdx.x == 0) {
        __threadfence();
        atomicAdd(&g_bar[i], 1u);
        while (*((volatile unsigned*)&g_bar[i]) < (unsigned)nblk) __nanosleep(32);
        __threadfence();
    }
    __syncthreads();
}

__device__ __forceinline__ void tile_of(int u, int& layer, int& ntile, int& kst, int& tend) {
    if (u < 512)       { layer = 0; ntile = u >> 6; kst = (u & 63) * 16; tend = (ntile + 1) * 64; }
    else if (u < 1536) { int r = u - 512;  layer = 1; ntile = r >> 7; kst = (r & 127) * 16; tend = 512 + (ntile + 1) * 128; }
    else               { int r = u - 1536; layer = 2; ntile = r >> 7; kst = (r & 127) * 16; tend = 1536 + (ntile + 1) * 128; }
}

// Persistent recurrence: 512 threads/block, 1 block/SM, weights resident in smem.
__global__ void __launch_bounds__(512) persist_kernel(int nblk) {
    extern __shared__ float sm_[];
    float* As_ = sm_;                 // double-buffered H staging: 2 x [64][PAD]
    float* Ws_ = sm_ + 2 * 64 * PAD;  // weight units, UFLOATS each
    __shared__ int tblP[24][24];
    __shared__ int tblCnt[24];
    const int tid = threadIdx.x, bid = blockIdx.x;
    const int warp = tid >> 5, lane = tid & 31;
    const int gid = lane >> 2, tig = lane & 3;
    const int u0 = ustart(bid, nblk), u1 = ustart(bid + 1, nblk);

    if (tid < 24) {
        int g = tid, t0, t1;
        if (g < 8)       { t0 = g * 64;                t1 = t0 + 64; }
        else if (g < 16) { t0 = 512 + (g - 8) * 128;   t1 = t0 + 128; }
        else             { t0 = 1536 + (g - 16) * 128; t1 = t0 + 128; }
        int cnt = 0;
        for (int bb = 0; bb < nblk; bb++) {
            int s0 = ustart(bb, nblk), s1 = ustart(bb + 1, nblk);
            if (s0 < t1 && s1 > t0) {
                int seg = (s0 < t0) ? 1 : 0;
                tblP[g][cnt++] = (bb * 2 + seg) * 8192;
            }
        }
        tblCnt[g] = cnt;
    }

    // ---- load this block's weight slab into smem (once) ----
    for (int j = 0; j < u1 - u0; j++) {
        int layer, ntile, kst, tend;
        tile_of(u0 + j, layer, ntile, kst, tend);
        const float* wsrc = (layer == 0) ? g_Wr0 : (layer == 1) ? g_Wr1 : g_Wr2;
        int K = (layer == 0) ? 1024 : 2048;
        int e = tid * 4, n = e >> 4, k0 = e & 15;
        float4 v = *(const float4*)&wsrc[(ntile * 128 + n) * K + kst + k0];
        *(float4*)&Ws_[j * UFLOATS + n * PAD + k0] = v;
    }
    __syncthreads();

    // precompute this thread's reduce-item geometry (static across slots)
    const int idx = bid * 512 + tid;
    const bool has_item = (idx < 49152);
    int r_g = 0, r_layer = 0, r_b = 0, r_nl4 = 0, r_nbase = 0;
    if (has_item) {
        r_g = idx >> 11;
        int e = idx & 2047;
        r_layer = r_g >> 3;
        r_b = e >> 5;
        r_nl4 = (e & 31) * 4;
        r_nbase = (r_g & 7) * 128;
    }

    int pp = 0;   // H-staging parity
    for (int s = 0; s < 258; s++) {
        // ---- prefetch reduce A input (independent of this slot's gemm) ----
        bool rvalid = false;
        float4 sumA;
        if (has_item) {
            rvalid = (r_layer == 0) ? (s <= 255)
                   : (r_layer == 1) ? (s >= 2 && s <= 256)
                                    : (s >= 5 && s <= 257);
            if (rvalid) {
                const float* A = (r_layer == 0) ? g_A0 : (r_layer == 1) ? g_A1 : g_A2;
                int t = (r_layer == 0) ? s : (r_layer == 1) ? (s - 1) : (s - 2);
                sumA = __ldcg((const float4*)&A[t * HB + r_b * 1024 + r_nbase + r_nl4]);
            }
        }

        // ================= GEMM phase =================
        int u = u0, seg = 0;
        while (u < u1) {
            int layer, ntile, kst, tend;
            tile_of(u, layer, ntile, kst, tend);
            int uend = (u1 < tend) ? u1 : tend;
            bool valid = (layer == 0) ? (s <= 255)
                       : (layer == 1) ? (s >= 2 && s <= 256)
                                      : (s >= 5 && s <= 257);
            if (valid) {
                const float *hA, *hB = 0;
                if (layer == 0)      { hA = g_H0 + s * HB; }
                else if (layer == 1) { hA = g_H0 + s * HB;       hB = g_H1 + (s - 2) * HB; }
                else                 { hA = g_H1 + (s - 2) * HB; hB = g_H2 + (s - 3) * HB; }

                const int arow = tid >> 2, aq = tid & 3;
                int steps = uend - u;
                int wbase = u - u0;

                float acc[4][4];
#pragma unroll
                for (int mi = 0; mi < 4; mi++)
#pragma unroll
                    for (int q = 0; q < 4; q++) acc[mi][q] = 0.f;

                float4 arv;
                if (tid < 256) {
                    int kg = kst + aq * 4;
                    arv = (layer == 0 || kg < 1024)
                        ? __ldcg((const float4*)(hA + arow * 1024 + kg))
                        : __ldcg((const float4*)(hB + arow * 1024 + kg - 1024));
                }
                for (int step = 0; step < steps; step++) {
                    if (tid < 256)
                        *(float4*)&As_[pp * 64 * PAD + arow * PAD + aq * 4] = arv;
                    __syncthreads();
                    if (step + 1 < steps && tid < 256) {
                        int kg2 = kst + (step + 1) * 16 + aq * 4;
                        arv = (layer == 0 || kg2 < 1024)
                            ? __ldcg((const float4*)(hA + arow * 1024 + kg2))
                            : __ldcg((const float4*)(hB + arow * 1024 + kg2 - 1024));
                    }
                    const float* wb = Ws_ + (wbase + step) * UFLOATS;
                    const float* ab = As_ + pp * 64 * PAD;
#pragma unroll
                    for (int sub = 0; sub < 2; sub++) {
                        int ko = sub * 8 + tig;
                        unsigned a[4][4], b[2];
                        int n0 = warp * 8 + gid;
                        b[0] = __float_as_uint(wb[n0 * PAD + ko]);
                        b[1] = __float_as_uint(wb[n0 * PAD + ko + 4]);
#pragma unroll
                        for (int mi = 0; mi < 4; mi++) {
                            int r0 = mi * 16 + gid;
                            a[mi][0] = __float_as_uint(ab[r0 * PAD + ko]);
                            a[mi][1] = __float_as_uint(ab[(r0 + 8) * PAD + ko]);
                            a[mi][2] = __float_as_uint(ab[r0 * PAD + ko + 4]);
                            a[mi][3] = __float_as_uint(ab[(r0 + 8) * PAD + ko + 4]);
                        }
#pragma unroll
                        for (int mi = 0; mi < 4; mi++) MMA_TF32(acc[mi], a[mi], b);
                    }
                    pp ^= 1;
                }
                float* pb = g_P + (bid * 2 + seg) * 8192;
#pragma unroll
                for (int mi = 0; mi < 4; mi++) {
                    int n = warp * 8 + 2 * tig;
                    int b0 = mi * 16 + gid;
                    *(float2*)&pb[b0 * 128 + n]       = make_float2(acc[mi][0], acc[mi][1]);
                    *(float2*)&pb[(b0 + 8) * 128 + n] = make_float2(acc[mi][2], acc[mi][3]);
                }
            }
            u = uend;
            seg++;
        }
        gbar(2 * s, nblk);

        // ================= reduce phase =================
        if (rvalid) {
            float4 sum = sumA;
            int cnt = tblCnt[r_g];
            for (int j = 0; j < cnt; j++) {
                float4 p = __ldcg((const float4*)&g_P[tblP[r_g][j] + r_b * 128 + r_nl4]);
                sum.x += p.x; sum.y += p.y; sum.z += p.z; sum.w += p.w;
            }
            float* dst = (r_layer == 0) ? (g_H0 + (s + 1) * HB)
                       : (r_layer == 1) ? (g_H1 + (s - 1) * HB)
                                        : (g_H2 + (s - 2) * HB);
            *(float4*)&dst[r_b * 1024 + r_nbase + r_nl4] = make_float4(
                rnd_tf32(tanhf(sum.x)), rnd_tf32(tanhf(sum.y)),
                rnd_tf32(tanhf(sum.z)), rnd_tf32(tanhf(sum.w)));
        }
        gbar(2 * s + 1, nblk);
    }
}

// out[l][b][i] = sum_h hs[b][h]*Wo[i][h] + bo[i]
__global__ void __launch_bounds__(256) out_kernel(const float* __restrict__ Wo,
                                                  const float* __restrict__ bo,
                                                  float* __restrict__ out) {
    __shared__ float Hs[64][65];
    __shared__ float Wos[32][65];
    const int l = blockIdx.y, ibase = blockIdx.x * 32;
    const float* hsrc = (l == 0) ? g_H0 + 256 * HB : (l == 1) ? g_H1 + 255 * HB : g_H2 + 255 * HB;
    const int tid = threadIdx.x, i = tid & 31, brow = tid >> 5;
    float acc[8];
#pragma unroll
    for (int q = 0; q < 8; q++) acc[q] = 0.f;
    for (int kc = 0; kc < 1024; kc += 64) {
        __syncthreads();
#pragma unroll
        for (int j = 0; j < 16; j++) {
            int e = j * 256 + tid, b = e >> 6, k = e & 63;
            Hs[b][k] = hsrc[b * 1024 + kc + k];
        }
#pragma unroll
        for (int j = 0; j < 8; j++) {
            int e = j * 256 + tid, ii = e >> 6, k = e & 63;
            Wos[ii][k] = Wo[(ibase + ii) * 1024 + kc + k];
        }
        __syncthreads();
#pragma unroll
        for (int k = 0; k < 64; k++) {
            float w = Wos[i][k];
#pragma unroll
            for (int bb = 0; bb < 8; bb++) acc[bb] += Hs[bb * 8 + brow][k] * w;
        }
    }
    float bv = bo[ibase + i];
#pragma unroll
    for (int bb = 0; bb < 8; bb++)
        out[l * 32768 + (bb * 8 + brow) * 512 + ibase + i] = acc[bb] + bv;
}

extern "C" void kernel_launch(void* const* d_in, const int* in_sizes, int n_in,
                              void* d_out, int out_size) {
    const float* x     = (const float*)d_in[0];
    const float* noise = (const float*)d_in[1];
    const float* Wi0   = (const float*)d_in[2];
    const float* Wi12  = (const float*)d_in[3];
    const float* bi    = (const float*)d_in[4];
    const float* Ws    = (const float*)d_in[5];
    const float* bs    = (const float*)d_in[6];
    const float* Wh    = (const float*)d_in[7];
    const float* bh    = (const float*)d_in[8];
    const float* Wo    = (const float*)d_in[9];
    const float* bo    = (const float*)d_in[10];
    float* out = (float*)d_out;

    int dev = 0, sm = 148;
    cudaGetDevice(&dev);
    cudaDeviceGetAttribute(&sm, cudaDevAttrMultiProcessorCount, dev);
    int nblk = sm;
    if (nblk > 296) nblk = 296;
    if (nblk < 1) nblk = 1;

    int maxu = (NU + nblk - 1) / nblk;            // max weight units per block
    size_t smemB = (size_t)(2 * 64 * PAD + (maxu + 1) * UFLOATS) * sizeof(float);
    static int smem_set = 0;
    if (!smem_set) {
        cudaFuncSetAttribute(persist_kernel,
                             cudaFuncAttributeMaxDynamicSharedMemorySize, (int)smemB);
        smem_set = 1;
    }

    prep_kernel<<<512, 256>>>(Wi0, Wi12, bi, Ws, bs, Wh, bh, noise);
    xcomb_kernel<<<24576, 256>>>(x);
    gemmA_mma_kernel<<<dim3(8, 256, 3), 256>>>();
    persist_kernel<<<nblk, 512, smemB>>>(nblk);
    out_kernel<<<dim3(16, 3), 256>>>(Wo, bo, out);
}